// round 3
// baseline (speedup 1.0000x reference)
#include <cuda_runtime.h>
#include <cstdint>

#define LLEN 4096
#define BATCH 32
#define COUT 256
#define CIN1 128
#define NELEM (BATCH*COUT*LLEN)   // 33554432

// ---------------- scratch (device globals; no allocation allowed) ----------------
__device__ __align__(16) float g_y1[NELEM];          // conv1 output
__device__ __align__(16) float g_s1[NELEM];          // lif1 output (conv2 input)
__device__ __align__(16) float g_y2[NELEM];          // conv2 output
__device__ __align__(16) float g_r [NELEM];          // ds conv output
__device__ __align__(16) float g_wt1[CIN1*3*COUT];   // transposed weights [ci][k][co]
__device__ __align__(16) float g_wt2[COUT*3*COUT];
__device__ __align__(16) float g_wtd[CIN1*1*COUT];
__device__ __align__(16) float g_stats[3*512];       // per-bn: [2*c]=sum, [2*c+1]=sumsq
__device__ __align__(16) float2 g_aff[3*256];        // per-bn per-channel (scale, shift)

// ---------------- small kernels ----------------
__global__ void clear_stats_kernel(float* __restrict__ stats) {
    int i = blockIdx.x * 256 + threadIdx.x;
    if (i < 3*512) stats[i] = 0.0f;
}

// w[co][ci][k] -> wt[(ci*KW+k)*COUT + co]
__global__ void transpose_w_kernel(const float* __restrict__ w, float* __restrict__ wt,
                                   int CIN, int KW) {
    int idx = blockIdx.x * 256 + threadIdx.x;
    int total = COUT * CIN * KW;
    if (idx >= total) return;
    int k  = idx % KW;
    int ci = (idx / KW) % CIN;
    int co = idx / (KW * CIN);
    wt[(ci*KW + k)*COUT + co] = w[idx];
}

__global__ void finalize_bn_kernel(const float* __restrict__ stats,
                                   const float* __restrict__ gamma,
                                   const float* __restrict__ beta,
                                   float2* __restrict__ aff) {
    int c = threadIdx.x;
    if (c < 256) {
        const float inv_n = 1.0f / (float)(BATCH * LLEN);
        float mean = stats[2*c]   * inv_n;
        float var  = stats[2*c+1] * inv_n - mean * mean;
        float sc = gamma[c] * rsqrtf(var + 1e-5f);
        float sh = beta[c] - mean * sc;
        aff[c] = make_float2(sc, sh);
    }
}

// ---------------- LIF (exact arithmetic mirror of the reference) ----------------
__device__ __forceinline__ float lif_mean_f(float c) {
    float v = 0.0f, cnt = 0.0f;
#pragma unroll
    for (int t = 0; t < 8; t++) {
        // v = v + (c - v)/2 ; (c-v)*0.5 is exact, so single fma == reference rounding
        v = __fmaf_rn(c - v, 0.5f, v);
        bool spk = (v >= 1.0f);       // == (v - 1.0 >= 0) exactly (Sterbenz)
        cnt += spk ? 1.0f : 0.0f;
        v = spk ? 0.0f : v;           // hard reset
    }
    return cnt * 0.125f;              // exact
}

__global__ void lif_kernel(const float4* __restrict__ y, const float2* __restrict__ aff,
                           float4* __restrict__ out) {
    int idx = blockIdx.x * 256 + threadIdx.x;        // NELEM/4 entries
    int c = (idx >> 10) & 255;                        // (idx*4 / L) % COUT, L/4 = 1024
    float2 a = aff[c];
    float4 v = y[idx];
    float4 o;
    o.x = lif_mean_f(__fmaf_rn(v.x, a.x, a.y));
    o.y = lif_mean_f(__fmaf_rn(v.y, a.x, a.y));
    o.z = lif_mean_f(__fmaf_rn(v.z, a.x, a.y));
    o.w = lif_mean_f(__fmaf_rn(v.w, a.x, a.y));
    out[idx] = o;
}

__global__ void final_kernel(const float4* __restrict__ y2, const float4* __restrict__ r,
                             const float2* __restrict__ aff2, const float2* __restrict__ affd,
                             float4* __restrict__ out) {
    int idx = blockIdx.x * 256 + threadIdx.x;
    int c = (idx >> 10) & 255;
    float2 a = aff2[c];
    float2 d = affd[c];
    float4 v = y2[idx];
    float4 rv = r[idx];
    float4 o;
    o.x = lif_mean_f(__fmaf_rn(v.x, a.x, a.y)) + __fmaf_rn(rv.x, d.x, d.y);
    o.y = lif_mean_f(__fmaf_rn(v.y, a.x, a.y)) + __fmaf_rn(rv.y, d.x, d.y);
    o.z = lif_mean_f(__fmaf_rn(v.z, a.x, a.y)) + __fmaf_rn(rv.z, d.x, d.y);
    o.w = lif_mean_f(__fmaf_rn(v.w, a.x, a.y)) + __fmaf_rn(rv.w, d.x, d.y);
    out[idx] = o;
}

// ---------------- conv1d ("same" padding) + fused per-channel stats ----------------
// Block: 128 cout x 64 L for one batch. 256 threads; per-thread 8 co x 4 L registers.
template<int CIN, int KW>
__global__ void __launch_bounds__(256) conv_bn_kernel(
    const float* __restrict__ x, const float* __restrict__ wT,
    const float* __restrict__ bias, float* __restrict__ y,
    float* __restrict__ stats)
{
    constexpr int TL = 64, TCO = 128, CCH = 8;
    constexpr int XW = TL + KW - 1;                 // 66 (K=3) / 64 (K=1)
    __shared__ __align__(16) float xs[CCH][72];     // padded row stride, 16B aligned
    __shared__ __align__(16) float ws[CCH][KW][TCO];

    const int tid = threadIdx.x;
    const int tl  = tid & 15;       // L-group (4 L each)
    const int cot = tid >> 4;       // co-group (8 co each)
    const int l0  = blockIdx.x * TL;
    const int co0 = blockIdx.y * TCO;
    const int b   = blockIdx.z;
    const float* xb = x + (size_t)b * CIN * LLEN;

    float acc[8][4];
#pragma unroll
    for (int i = 0; i < 8; i++)
#pragma unroll
        for (int j = 0; j < 4; j++) acc[i][j] = 0.0f;

    for (int ci0 = 0; ci0 < CIN; ci0 += CCH) {
        __syncthreads();
        // stage x window (zero-padded at sequence edges)
        for (int i = tid; i < CCH * XW; i += 256) {
            int cl = i / XW, j = i - cl * XW;
            int gl = l0 + j - (KW / 2);
            float v = 0.0f;
            if (gl >= 0 && gl < LLEN) v = xb[(ci0 + cl) * LLEN + gl];
            xs[cl][j] = v;
        }
        // stage weights (coalesced from transposed layout)
        for (int i = tid; i < CCH * KW * TCO; i += 256) {
            int col = i & (TCO - 1);
            int rest = i >> 7;
            int k = rest % KW;
            int cl = rest / KW;
            ws[cl][k][col] = wT[((ci0 + cl) * KW + k) * COUT + co0 + col];
        }
        __syncthreads();
#pragma unroll
        for (int cl = 0; cl < CCH; cl++) {
            float xv[KW + 3];
            float4 x4 = *reinterpret_cast<const float4*>(&xs[cl][tl * 4]);
            xv[0] = x4.x; xv[1] = x4.y; xv[2] = x4.z; xv[3] = x4.w;
            if constexpr (KW == 3) {
                xv[4] = xs[cl][tl * 4 + 4];
                xv[5] = xs[cl][tl * 4 + 5];
            }
#pragma unroll
            for (int k = 0; k < KW; k++) {
                float4 wa = *reinterpret_cast<const float4*>(&ws[cl][k][cot * 8]);
                float4 wb = *reinterpret_cast<const float4*>(&ws[cl][k][cot * 8 + 4]);
                float wv[8] = {wa.x, wa.y, wa.z, wa.w, wb.x, wb.y, wb.z, wb.w};
#pragma unroll
                for (int i = 0; i < 8; i++)
#pragma unroll
                    for (int j = 0; j < 4; j++)
                        acc[i][j] = __fmaf_rn(wv[i], xv[j + k], acc[i][j]);
            }
        }
    }

    // epilogue: bias, store, per-channel sum/sumsq reduction
#pragma unroll
    for (int i = 0; i < 8; i++) {
        int co = co0 + cot * 8 + i;
        float bv = bias[co];
        float s = 0.0f, q = 0.0f;
#pragma unroll
        for (int j = 0; j < 4; j++) {
            acc[i][j] += bv;
            s += acc[i][j];
            q = __fmaf_rn(acc[i][j], acc[i][j], q);
        }
        float4 o = make_float4(acc[i][0], acc[i][1], acc[i][2], acc[i][3]);
        *reinterpret_cast<float4*>(&y[((size_t)b * COUT + co) * LLEN + l0 + tl * 4]) = o;
#pragma unroll
        for (int off = 8; off; off >>= 1) {
            s += __shfl_down_sync(0xffffffffu, s, off, 16);
            q += __shfl_down_sync(0xffffffffu, q, off, 16);
        }
        if (tl == 0) {
            atomicAdd(&stats[2 * co],     s);
            atomicAdd(&stats[2 * co + 1], q);
        }
    }
}

// ---------------- launch ----------------
extern "C" void kernel_launch(void* const* d_in, const int* in_sizes, int n_in,
                              void* d_out, int out_size) {
    const float* x   = (const float*)d_in[0];
    const float* w1  = (const float*)d_in[1];
    const float* b1  = (const float*)d_in[2];
    const float* g1  = (const float*)d_in[3];
    const float* be1 = (const float*)d_in[4];
    const float* w2  = (const float*)d_in[5];
    const float* b2  = (const float*)d_in[6];
    const float* g2  = (const float*)d_in[7];
    const float* be2 = (const float*)d_in[8];
    const float* wd  = (const float*)d_in[9];
    const float* bd  = (const float*)d_in[10];
    const float* gd  = (const float*)d_in[11];
    const float* bed = (const float*)d_in[12];
    float* out = (float*)d_out;
    (void)in_sizes; (void)n_in; (void)out_size;   // T = 8 (hardcoded, shapes fixed)

    float *y1, *s1, *y2, *r, *wt1, *wt2, *wtd, *stats;
    float2* aff;
    cudaGetSymbolAddress((void**)&y1,  g_y1);
    cudaGetSymbolAddress((void**)&s1,  g_s1);
    cudaGetSymbolAddress((void**)&y2,  g_y2);
    cudaGetSymbolAddress((void**)&r,   g_r);
    cudaGetSymbolAddress((void**)&wt1, g_wt1);
    cudaGetSymbolAddress((void**)&wt2, g_wt2);
    cudaGetSymbolAddress((void**)&wtd, g_wtd);
    cudaGetSymbolAddress((void**)&stats, g_stats);
    cudaGetSymbolAddress((void**)&aff, g_aff);

    clear_stats_kernel<<<6, 256>>>(stats);
    transpose_w_kernel<<<(CIN1*3*COUT + 255)/256, 256>>>(w1, wt1, CIN1, 3);
    transpose_w_kernel<<<(COUT*3*COUT + 255)/256, 256>>>(w2, wt2, COUT, 3);
    transpose_w_kernel<<<(CIN1*1*COUT + 255)/256, 256>>>(wd, wtd, CIN1, 1);

    dim3 cgrid(LLEN/64, COUT/128, BATCH);
    // conv1 + stats ; ds conv (1x1) + stats
    conv_bn_kernel<CIN1, 3><<<cgrid, 256>>>(x, wt1, b1, y1, stats);
    conv_bn_kernel<CIN1, 1><<<cgrid, 256>>>(x, wtd, bd, r,  stats + 1024);
    finalize_bn_kernel<<<1, 256>>>(stats,        g1, be1, aff);        // bn1
    finalize_bn_kernel<<<1, 256>>>(stats + 1024, gd, bed, aff + 512);  // bnd
    // LIF stage 1
    lif_kernel<<<NELEM/1024, 256>>>((const float4*)y1, aff, (float4*)s1);
    // conv2 + stats
    conv_bn_kernel<COUT, 3><<<cgrid, 256>>>(s1, wt2, b2, y2, stats + 512);
    finalize_bn_kernel<<<1, 256>>>(stats + 512, g2, be2, aff + 256);   // bn2
    // LIF stage 2 + residual add
    final_kernel<<<NELEM/1024, 256>>>((const float4*)y2, (const float4*)r,
                                      aff + 256, aff + 512, (float4*)out);
}

// round 5
// speedup vs baseline: 1.1727x; 1.1727x over previous
#include <cuda_runtime.h>
#include <cstdint>

#define LLEN 4096
#define BATCH 32
#define COUT 256
#define CIN1 128
#define NELEM (BATCH*COUT*LLEN)   // 33554432

// ---- packed f32x2 helpers (Blackwell FFMA2 path, PTX-only) ----
#define PACK2(out, lo, hi)  asm("mov.b64 %0, {%1, %2};" : "=l"(out) : "f"(lo), "f"(hi))
#define UNPACK2(lo, hi, in) asm("mov.b64 {%0, %1}, %2;" : "=f"(lo), "=f"(hi) : "l"(in))
#define FMA2(d, a, b, c)    asm("fma.rn.f32x2 %0, %1, %2, %3;" : "=l"(d) : "l"(a), "l"(b), "l"(c))

// ---------------- scratch (device globals; no allocation allowed) ----------------
__device__ __align__(16) float g_y1[NELEM];          // conv1 output
__device__ __align__(16) float g_s1[NELEM];          // lif1 output (conv2 input)
__device__ __align__(16) float g_y2[NELEM];          // conv2 output
__device__ __align__(16) float g_r [NELEM];          // ds conv output
__device__ __align__(16) float g_wt1[CIN1*3*COUT];   // transposed weights [ci][k][co]
__device__ __align__(16) float g_wt2[COUT*3*COUT];
__device__ __align__(16) float g_wtd[CIN1*1*COUT];
__device__ __align__(16) float g_stats[3*512];       // per-bn: [2*c]=sum, [2*c+1]=sumsq
__device__ __align__(16) float2 g_aff[3*256];        // per-bn per-channel (scale, shift)

// ---------------- small kernels ----------------
__global__ void clear_stats_kernel(float* __restrict__ stats) {
    int i = blockIdx.x * 256 + threadIdx.x;
    if (i < 3*512) stats[i] = 0.0f;
}

// w[co][ci][k] -> wt[(ci*KW+k)*COUT + co]
__global__ void transpose_w_kernel(const float* __restrict__ w, float* __restrict__ wt,
                                   int CIN, int KW) {
    int idx = blockIdx.x * 256 + threadIdx.x;
    int total = COUT * CIN * KW;
    if (idx >= total) return;
    int k  = idx % KW;
    int ci = (idx / KW) % CIN;
    int co = idx / (KW * CIN);
    wt[(ci*KW + k)*COUT + co] = w[idx];
}

__global__ void finalize_bn_kernel(const float* __restrict__ stats,
                                   const float* __restrict__ gamma,
                                   const float* __restrict__ beta,
                                   float2* __restrict__ aff) {
    int c = threadIdx.x;
    if (c < 256) {
        const float inv_n = 1.0f / (float)(BATCH * LLEN);
        float mean = stats[2*c]   * inv_n;
        float var  = stats[2*c+1] * inv_n - mean * mean;
        float sc = gamma[c] * rsqrtf(var + 1e-5f);
        float sh = beta[c] - mean * sc;
        aff[c] = make_float2(sc, sh);
    }
}

// ---------------- LIF (exact arithmetic mirror of the reference) ----------------
__device__ __forceinline__ float lif_mean_f(float c) {
    float v = 0.0f, cnt = 0.0f;
#pragma unroll
    for (int t = 0; t < 8; t++) {
        v = __fmaf_rn(c - v, 0.5f, v);   // == v + (c-v)/2 with reference rounding
        bool spk = (v >= 1.0f);
        cnt += spk ? 1.0f : 0.0f;
        v = spk ? 0.0f : v;
    }
    return cnt * 0.125f;
}

__global__ void lif_kernel(const float4* __restrict__ y, const float2* __restrict__ aff,
                           float4* __restrict__ out) {
    int idx = blockIdx.x * 256 + threadIdx.x;        // NELEM/4 entries
    int c = (idx >> 10) & 255;                        // (idx*4 / L) % COUT
    float2 a = aff[c];
    float4 v = y[idx];
    float4 o;
    o.x = lif_mean_f(__fmaf_rn(v.x, a.x, a.y));
    o.y = lif_mean_f(__fmaf_rn(v.y, a.x, a.y));
    o.z = lif_mean_f(__fmaf_rn(v.z, a.x, a.y));
    o.w = lif_mean_f(__fmaf_rn(v.w, a.x, a.y));
    out[idx] = o;
}

__global__ void final_kernel(const float4* __restrict__ y2, const float4* __restrict__ r,
                             const float2* __restrict__ aff2, const float2* __restrict__ affd,
                             float4* __restrict__ out) {
    int idx = blockIdx.x * 256 + threadIdx.x;
    int c = (idx >> 10) & 255;
    float2 a = aff2[c];
    float2 d = affd[c];
    float4 v = y2[idx];
    float4 rv = r[idx];
    float4 o;
    o.x = lif_mean_f(__fmaf_rn(v.x, a.x, a.y)) + __fmaf_rn(rv.x, d.x, d.y);
    o.y = lif_mean_f(__fmaf_rn(v.y, a.x, a.y)) + __fmaf_rn(rv.y, d.x, d.y);
    o.z = lif_mean_f(__fmaf_rn(v.z, a.x, a.y)) + __fmaf_rn(rv.z, d.x, d.y);
    o.w = lif_mean_f(__fmaf_rn(v.w, a.x, a.y)) + __fmaf_rn(rv.w, d.x, d.y);
    out[idx] = o;
}

// ---------------- conv1d ("same" padding) + fused per-channel stats ----------------
// Block: 128 cout x 64 L for one batch. 256 threads; per-thread 8 co x 4 L registers,
// held as 4 co-PAIRS x 4 L packed f32x2 accumulators (FFMA2 path).
template<int CIN, int KW>
__global__ void __launch_bounds__(256) conv_bn_kernel(
    const float* __restrict__ x, const float* __restrict__ wT,
    const float* __restrict__ bias, float* __restrict__ y,
    float* __restrict__ stats)
{
    constexpr int TL = 64, TCO = 128, CCH = 8;
    constexpr int XW = TL + KW - 1;                 // 66 (K=3) / 64 (K=1)
    constexpr int NXV = KW + 3;
    __shared__ __align__(16) float xs[CCH][72];     // padded row stride, 16B aligned
    __shared__ __align__(16) float ws[CCH][KW][TCO];

    const int tid = threadIdx.x;
    const int tl  = tid & 15;       // L-group (4 L each)
    const int cot = tid >> 4;       // co-group (8 co each)
    const int l0  = blockIdx.x * TL;
    const int co0 = blockIdx.y * TCO;
    const int b   = blockIdx.z;
    const float* xb = x + (size_t)b * CIN * LLEN;

    unsigned long long accp[4][4];   // [co-pair][L], lo = even co, hi = odd co
#pragma unroll
    for (int i = 0; i < 4; i++)
#pragma unroll
        for (int j = 0; j < 4; j++) accp[i][j] = 0ull;

    for (int ci0 = 0; ci0 < CIN; ci0 += CCH) {
        __syncthreads();
        // stage x window (zero-padded at sequence edges)
        for (int i = tid; i < CCH * XW; i += 256) {
            int cl = i / XW, j = i - cl * XW;
            int gl = l0 + j - (KW / 2);
            float v = 0.0f;
            if (gl >= 0 && gl < LLEN) v = xb[(ci0 + cl) * LLEN + gl];
            xs[cl][j] = v;
        }
        // stage weights (coalesced from transposed layout)
        for (int i = tid; i < CCH * KW * TCO; i += 256) {
            int col = i & (TCO - 1);
            int rest = i >> 7;
            int k = rest % KW;
            int cl = rest / KW;
            ws[cl][k][col] = wT[((ci0 + cl) * KW + k) * COUT + co0 + col];
        }
        __syncthreads();
#pragma unroll
        for (int cl = 0; cl < CCH; cl++) {
            float xv[NXV];
            float4 x4 = *reinterpret_cast<const float4*>(&xs[cl][tl * 4]);
            xv[0] = x4.x; xv[1] = x4.y; xv[2] = x4.z; xv[3] = x4.w;
            if constexpr (KW == 3) {
                xv[4] = xs[cl][tl * 4 + 4];
                xv[5] = xs[cl][tl * 4 + 5];
            }
            // replicate x into both f32x2 lanes (only pack cost in the loop)
            unsigned long long xp[NXV];
#pragma unroll
            for (int j = 0; j < NXV; j++) PACK2(xp[j], xv[j], xv[j]);
#pragma unroll
            for (int k = 0; k < KW; k++) {
                // consecutive-co weight pairs come pre-packed from LDS.128
                ulonglong2 wA = *reinterpret_cast<const ulonglong2*>(&ws[cl][k][cot * 8]);
                ulonglong2 wB = *reinterpret_cast<const ulonglong2*>(&ws[cl][k][cot * 8 + 4]);
                unsigned long long wp[4] = {wA.x, wA.y, wB.x, wB.y};
#pragma unroll
                for (int i = 0; i < 4; i++)
#pragma unroll
                    for (int j = 0; j < 4; j++)
                        FMA2(accp[i][j], wp[i], xp[j + k], accp[i][j]);
            }
        }
    }

    // unpack to scalar accumulators (lane order: lo = even co = 2i, hi = 2i+1)
    float acc[8][4];
#pragma unroll
    for (int i = 0; i < 4; i++)
#pragma unroll
        for (int j = 0; j < 4; j++)
            UNPACK2(acc[2 * i][j], acc[2 * i + 1][j], accp[i][j]);

    // epilogue: bias, store, per-channel sum/sumsq reduction
#pragma unroll
    for (int i = 0; i < 8; i++) {
        int co = co0 + cot * 8 + i;
        float bv = bias[co];
        float s = 0.0f, q = 0.0f;
#pragma unroll
        for (int j = 0; j < 4; j++) {
            acc[i][j] += bv;
            s += acc[i][j];
            q = __fmaf_rn(acc[i][j], acc[i][j], q);
        }
        float4 o = make_float4(acc[i][0], acc[i][1], acc[i][2], acc[i][3]);
        *reinterpret_cast<float4*>(&y[((size_t)b * COUT + co) * LLEN + l0 + tl * 4]) = o;
#pragma unroll
        for (int off = 8; off; off >>= 1) {
            s += __shfl_down_sync(0xffffffffu, s, off, 16);
            q += __shfl_down_sync(0xffffffffu, q, off, 16);
        }
        if (tl == 0) {
            atomicAdd(&stats[2 * co],     s);
            atomicAdd(&stats[2 * co + 1], q);
        }
    }
}

// ---------------- launch ----------------
extern "C" void kernel_launch(void* const* d_in, const int* in_sizes, int n_in,
                              void* d_out, int out_size) {
    const float* x   = (const float*)d_in[0];
    const float* w1  = (const float*)d_in[1];
    const float* b1  = (const float*)d_in[2];
    const float* g1  = (const float*)d_in[3];
    const float* be1 = (const float*)d_in[4];
    const float* w2  = (const float*)d_in[5];
    const float* b2  = (const float*)d_in[6];
    const float* g2  = (const float*)d_in[7];
    const float* be2 = (const float*)d_in[8];
    const float* wd  = (const float*)d_in[9];
    const float* bd  = (const float*)d_in[10];
    const float* gd  = (const float*)d_in[11];
    const float* bed = (const float*)d_in[12];
    float* out = (float*)d_out;
    (void)in_sizes; (void)n_in; (void)out_size;   // T = 8 (hardcoded, shapes fixed)

    float *y1, *s1, *y2, *r, *wt1, *wt2, *wtd, *stats;
    float2* aff;
    cudaGetSymbolAddress((void**)&y1,  g_y1);
    cudaGetSymbolAddress((void**)&s1,  g_s1);
    cudaGetSymbolAddress((void**)&y2,  g_y2);
    cudaGetSymbolAddress((void**)&r,   g_r);
    cudaGetSymbolAddress((void**)&wt1, g_wt1);
    cudaGetSymbolAddress((void**)&wt2, g_wt2);
    cudaGetSymbolAddress((void**)&wtd, g_wtd);
    cudaGetSymbolAddress((void**)&stats, g_stats);
    cudaGetSymbolAddress((void**)&aff, g_aff);

    clear_stats_kernel<<<6, 256>>>(stats);
    transpose_w_kernel<<<(CIN1*3*COUT + 255)/256, 256>>>(w1, wt1, CIN1, 3);
    transpose_w_kernel<<<(COUT*3*COUT + 255)/256, 256>>>(w2, wt2, COUT, 3);
    transpose_w_kernel<<<(CIN1*1*COUT + 255)/256, 256>>>(wd, wtd, CIN1, 1);

    dim3 cgrid(LLEN/64, COUT/128, BATCH);
    // conv1 + stats ; ds conv (1x1) + stats
    conv_bn_kernel<CIN1, 3><<<cgrid, 256>>>(x, wt1, b1, y1, stats);
    conv_bn_kernel<CIN1, 1><<<cgrid, 256>>>(x, wtd, bd, r,  stats + 1024);
    finalize_bn_kernel<<<1, 256>>>(stats,        g1, be1, aff);        // bn1
    finalize_bn_kernel<<<1, 256>>>(stats + 1024, gd, bed, aff + 512);  // bnd
    // LIF stage 1
    lif_kernel<<<NELEM/1024, 256>>>((const float4*)y1, aff, (float4*)s1);
    // conv2 + stats
    conv_bn_kernel<COUT, 3><<<cgrid, 256>>>(s1, wt2, b2, y2, stats + 512);
    finalize_bn_kernel<<<1, 256>>>(stats + 512, g2, be2, aff + 256);   // bn2
    // LIF stage 2 + residual add
    final_kernel<<<NELEM/1024, 256>>>((const float4*)y2, (const float4*)r,
                                      aff + 256, aff + 512, (float4*)out);
}

// round 6
// speedup vs baseline: 1.1731x; 1.0004x over previous
#include <cuda_runtime.h>
#include <cstdint>

#define LLEN 4096
#define BATCH 32
#define COUT 256
#define CIN1 128
#define NELEM (BATCH*COUT*LLEN)   // 33554432

// ---- packed f32x2 helpers (Blackwell FFMA2 path, PTX-only) ----
#define PACK2(out, lo, hi)  asm("mov.b64 %0, {%1, %2};" : "=l"(out) : "f"(lo), "f"(hi))
#define UNPACK2(lo, hi, in) asm("mov.b64 {%0, %1}, %2;" : "=f"(lo), "=f"(hi) : "l"(in))
#define FMA2(d, a, b, c)    asm("fma.rn.f32x2 %0, %1, %2, %3;" : "=l"(d) : "l"(a), "l"(b), "l"(c))

// ---------------- scratch (device globals; no allocation allowed) ----------------
__device__ __align__(16) float g_y1[NELEM];          // conv1 output
__device__ __align__(16) float g_s1[NELEM];          // lif1 output (conv2 input)
__device__ __align__(16) float g_y2[NELEM];          // conv2 output
__device__ __align__(16) float g_r [NELEM];          // ds conv output
__device__ __align__(16) float g_wt1[CIN1*3*COUT];   // transposed weights [ci][k][co]
__device__ __align__(16) float g_wt2[COUT*3*COUT];
__device__ __align__(16) float g_wtd[CIN1*1*COUT];
__device__ __align__(16) float g_stats[3*512];       // per-bn: [2*c]=sum, [2*c+1]=sumsq
__device__ __align__(16) float2 g_aff[3*256];        // per-bn per-channel (scale, shift)

// ---------------- small kernels ----------------
__global__ void clear_stats_kernel(float* __restrict__ stats) {
    int i = blockIdx.x * 256 + threadIdx.x;
    if (i < 3*512) stats[i] = 0.0f;
}

// w[co][ci][k] -> wt[(ci*KW+k)*COUT + co]
__global__ void transpose_w_kernel(const float* __restrict__ w, float* __restrict__ wt,
                                   int CIN, int KW) {
    int idx = blockIdx.x * 256 + threadIdx.x;
    int total = COUT * CIN * KW;
    if (idx >= total) return;
    int k  = idx % KW;
    int ci = (idx / KW) % CIN;
    int co = idx / (KW * CIN);
    wt[(ci*KW + k)*COUT + co] = w[idx];
}

__global__ void finalize_bn_kernel(const float* __restrict__ stats,
                                   const float* __restrict__ gamma,
                                   const float* __restrict__ beta,
                                   float2* __restrict__ aff) {
    int c = threadIdx.x;
    if (c < 256) {
        const float inv_n = 1.0f / (float)(BATCH * LLEN);
        float mean = stats[2*c]   * inv_n;
        float var  = stats[2*c+1] * inv_n - mean * mean;
        float sc = gamma[c] * rsqrtf(var + 1e-5f);
        float sh = beta[c] - mean * sc;
        aff[c] = make_float2(sc, sh);
    }
}

// ---------------- LIF (exact arithmetic mirror of the reference) ----------------
__device__ __forceinline__ float lif_mean_f(float c) {
    float v = 0.0f, cnt = 0.0f;
#pragma unroll
    for (int t = 0; t < 8; t++) {
        v = __fmaf_rn(c - v, 0.5f, v);   // == v + (c-v)/2 with reference rounding
        bool spk = (v >= 1.0f);
        cnt += spk ? 1.0f : 0.0f;
        v = spk ? 0.0f : v;
    }
    return cnt * 0.125f;
}

__global__ void lif_kernel(const float4* __restrict__ y, const float2* __restrict__ aff,
                           float4* __restrict__ out) {
    int idx = blockIdx.x * 256 + threadIdx.x;        // NELEM/4 entries
    int c = (idx >> 10) & 255;                        // (idx*4 / L) % COUT
    float2 a = aff[c];
    float4 v = y[idx];
    float4 o;
    o.x = lif_mean_f(__fmaf_rn(v.x, a.x, a.y));
    o.y = lif_mean_f(__fmaf_rn(v.y, a.x, a.y));
    o.z = lif_mean_f(__fmaf_rn(v.z, a.x, a.y));
    o.w = lif_mean_f(__fmaf_rn(v.w, a.x, a.y));
    out[idx] = o;
}

__global__ void final_kernel(const float4* __restrict__ y2, const float4* __restrict__ r,
                             const float2* __restrict__ aff2, const float2* __restrict__ affd,
                             float4* __restrict__ out) {
    int idx = blockIdx.x * 256 + threadIdx.x;
    int c = (idx >> 10) & 255;
    float2 a = aff2[c];
    float2 d = affd[c];
    float4 v = y2[idx];
    float4 rv = r[idx];
    float4 o;
    o.x = lif_mean_f(__fmaf_rn(v.x, a.x, a.y)) + __fmaf_rn(rv.x, d.x, d.y);
    o.y = lif_mean_f(__fmaf_rn(v.y, a.x, a.y)) + __fmaf_rn(rv.y, d.x, d.y);
    o.z = lif_mean_f(__fmaf_rn(v.z, a.x, a.y)) + __fmaf_rn(rv.z, d.x, d.y);
    o.w = lif_mean_f(__fmaf_rn(v.w, a.x, a.y)) + __fmaf_rn(rv.w, d.x, d.y);
    out[idx] = o;
}

// ---------------- conv1d ("same" padding) + fused per-channel stats ----------------
// Block: 128 cout x 64 L for one batch. 256 threads; per-thread 8 co x 4 L registers,
// held as 4 co-PAIRS x 4 L packed f32x2 accumulators (FFMA2 path).
template<int CIN, int KW>
__global__ void __launch_bounds__(256) conv_bn_kernel(
    const float* __restrict__ x, const float* __restrict__ wT,
    const float* __restrict__ bias, float* __restrict__ y,
    float* __restrict__ stats)
{
    constexpr int TL = 64, TCO = 128, CCH = 8;
    constexpr int XW = TL + KW - 1;                 // 66 (K=3) / 64 (K=1)
    constexpr int NXV = KW + 3;
    __shared__ __align__(16) float xs[CCH][72];     // padded row stride, 16B aligned
    __shared__ __align__(16) float ws[CCH][KW][TCO];

    const int tid = threadIdx.x;
    const int tl  = tid & 15;       // L-group (4 L each)
    const int cot = tid >> 4;       // co-group (8 co each)
    const int l0  = blockIdx.x * TL;
    const int co0 = blockIdx.y * TCO;
    const int b   = blockIdx.z;
    const float* xb = x + (size_t)b * CIN * LLEN;

    unsigned long long accp[4][4];   // [co-pair][L], lo = even co, hi = odd co
#pragma unroll
    for (int i = 0; i < 4; i++)
#pragma unroll
        for (int j = 0; j < 4; j++) accp[i][j] = 0ull;

    for (int ci0 = 0; ci0 < CIN; ci0 += CCH) {
        __syncthreads();
        // stage x window (zero-padded at sequence edges)
        for (int i = tid; i < CCH * XW; i += 256) {
            int cl = i / XW, j = i - cl * XW;
            int gl = l0 + j - (KW / 2);
            float v = 0.0f;
            if (gl >= 0 && gl < LLEN) v = xb[(ci0 + cl) * LLEN + gl];
            xs[cl][j] = v;
        }
        // stage weights (coalesced from transposed layout)
        for (int i = tid; i < CCH * KW * TCO; i += 256) {
            int col = i & (TCO - 1);
            int rest = i >> 7;
            int k = rest % KW;
            int cl = rest / KW;
            ws[cl][k][col] = wT[((ci0 + cl) * KW + k) * COUT + co0 + col];
        }
        __syncthreads();
#pragma unroll
        for (int cl = 0; cl < CCH; cl++) {
            float xv[NXV];
            float4 x4 = *reinterpret_cast<const float4*>(&xs[cl][tl * 4]);
            xv[0] = x4.x; xv[1] = x4.y; xv[2] = x4.z; xv[3] = x4.w;
            if constexpr (KW == 3) {
                xv[4] = xs[cl][tl * 4 + 4];
                xv[5] = xs[cl][tl * 4 + 5];
            }
            // replicate x into both f32x2 lanes (only pack cost in the loop)
            unsigned long long xp[NXV];
#pragma unroll
            for (int j = 0; j < NXV; j++) PACK2(xp[j], xv[j], xv[j]);
#pragma unroll
            for (int k = 0; k < KW; k++) {
                // consecutive-co weight pairs come pre-packed from LDS.128
                ulonglong2 wA = *reinterpret_cast<const ulonglong2*>(&ws[cl][k][cot * 8]);
                ulonglong2 wB = *reinterpret_cast<const ulonglong2*>(&ws[cl][k][cot * 8 + 4]);
                unsigned long long wp[4] = {wA.x, wA.y, wB.x, wB.y};
#pragma unroll
                for (int i = 0; i < 4; i++)
#pragma unroll
                    for (int j = 0; j < 4; j++)
                        FMA2(accp[i][j], wp[i], xp[j + k], accp[i][j]);
            }
        }
    }

    // unpack to scalar accumulators (lane order: lo = even co = 2i, hi = 2i+1)
    float acc[8][4];
#pragma unroll
    for (int i = 0; i < 4; i++)
#pragma unroll
        for (int j = 0; j < 4; j++)
            UNPACK2(acc[2 * i][j], acc[2 * i + 1][j], accp[i][j]);

    // epilogue: bias, store, per-channel sum/sumsq reduction
#pragma unroll
    for (int i = 0; i < 8; i++) {
        int co = co0 + cot * 8 + i;
        float bv = bias[co];
        float s = 0.0f, q = 0.0f;
#pragma unroll
        for (int j = 0; j < 4; j++) {
            acc[i][j] += bv;
            s += acc[i][j];
            q = __fmaf_rn(acc[i][j], acc[i][j], q);
        }
        float4 o = make_float4(acc[i][0], acc[i][1], acc[i][2], acc[i][3]);
        *reinterpret_cast<float4*>(&y[((size_t)b * COUT + co) * LLEN + l0 + tl * 4]) = o;
#pragma unroll
        for (int off = 8; off; off >>= 1) {
            s += __shfl_down_sync(0xffffffffu, s, off, 16);
            q += __shfl_down_sync(0xffffffffu, q, off, 16);
        }
        if (tl == 0) {
            atomicAdd(&stats[2 * co],     s);
            atomicAdd(&stats[2 * co + 1], q);
        }
    }
}

// ---------------- launch ----------------
extern "C" void kernel_launch(void* const* d_in, const int* in_sizes, int n_in,
                              void* d_out, int out_size) {
    const float* x   = (const float*)d_in[0];
    const float* w1  = (const float*)d_in[1];
    const float* b1  = (const float*)d_in[2];
    const float* g1  = (const float*)d_in[3];
    const float* be1 = (const float*)d_in[4];
    const float* w2  = (const float*)d_in[5];
    const float* b2  = (const float*)d_in[6];
    const float* g2  = (const float*)d_in[7];
    const float* be2 = (const float*)d_in[8];
    const float* wd  = (const float*)d_in[9];
    const float* bd  = (const float*)d_in[10];
    const float* gd  = (const float*)d_in[11];
    const float* bed = (const float*)d_in[12];
    float* out = (float*)d_out;
    (void)in_sizes; (void)n_in; (void)out_size;   // T = 8 (hardcoded, shapes fixed)

    float *y1, *s1, *y2, *r, *wt1, *wt2, *wtd, *stats;
    float2* aff;
    cudaGetSymbolAddress((void**)&y1,  g_y1);
    cudaGetSymbolAddress((void**)&s1,  g_s1);
    cudaGetSymbolAddress((void**)&y2,  g_y2);
    cudaGetSymbolAddress((void**)&r,   g_r);
    cudaGetSymbolAddress((void**)&wt1, g_wt1);
    cudaGetSymbolAddress((void**)&wt2, g_wt2);
    cudaGetSymbolAddress((void**)&wtd, g_wtd);
    cudaGetSymbolAddress((void**)&stats, g_stats);
    cudaGetSymbolAddress((void**)&aff, g_aff);

    clear_stats_kernel<<<6, 256>>>(stats);
    transpose_w_kernel<<<(CIN1*3*COUT + 255)/256, 256>>>(w1, wt1, CIN1, 3);
    transpose_w_kernel<<<(COUT*3*COUT + 255)/256, 256>>>(w2, wt2, COUT, 3);
    transpose_w_kernel<<<(CIN1*1*COUT + 255)/256, 256>>>(wd, wtd, CIN1, 1);

    dim3 cgrid(LLEN/64, COUT/128, BATCH);
    // conv1 + stats ; ds conv (1x1) + stats
    conv_bn_kernel<CIN1, 3><<<cgrid, 256>>>(x, wt1, b1, y1, stats);
    conv_bn_kernel<CIN1, 1><<<cgrid, 256>>>(x, wtd, bd, r,  stats + 1024);
    finalize_bn_kernel<<<1, 256>>>(stats,        g1, be1, aff);        // bn1
    finalize_bn_kernel<<<1, 256>>>(stats + 1024, gd, bed, aff + 512);  // bnd
    // LIF stage 1
    lif_kernel<<<NELEM/1024, 256>>>((const float4*)y1, aff, (float4*)s1);
    // conv2 + stats
    conv_bn_kernel<COUT, 3><<<cgrid, 256>>>(s1, wt2, b2, y2, stats + 512);
    finalize_bn_kernel<<<1, 256>>>(stats + 512, g2, be2, aff + 256);   // bn2
    // LIF stage 2 + residual add
    final_kernel<<<NELEM/1024, 256>>>((const float4*)y2, (const float4*)r,
                                      aff + 256, aff + 512, (float4*)out);
}

// round 10
// speedup vs baseline: 1.6455x; 1.4027x over previous
#include <cuda_runtime.h>
#include <cstdint>

#define LLEN 4096
#define BATCH 32
#define COUT 256
#define CIN1 128
#define NELEM (BATCH*COUT*LLEN)   // 33554432

// ---- packed f32x2 helpers (Blackwell FFMA2 path, PTX-only) ----
#define PACK2(out, lo, hi)  asm("mov.b64 %0, {%1, %2};" : "=l"(out) : "f"(lo), "f"(hi))
#define UNPACK2(lo, hi, in) asm("mov.b64 {%0, %1}, %2;" : "=f"(lo), "=f"(hi) : "l"(in))
#define FMA2(d, a, b, c)    asm("fma.rn.f32x2 %0, %1, %2, %3;" : "=l"(d) : "l"(a), "l"(b), "l"(c))

// ---------------- scratch (device globals; no allocation allowed) ----------------
__device__ __align__(16) float g_y1[NELEM];          // conv1 output
__device__ __align__(16) float g_s1[NELEM];          // lif1 output (conv2 input)
__device__ __align__(16) float g_y2[NELEM];          // conv2 output
__device__ __align__(16) float g_r [NELEM];          // ds conv output
__device__ __align__(16) float g_wt1[CIN1*3*COUT];   // transposed weights [ci][k][co]
__device__ __align__(16) float g_wt2[COUT*3*COUT];
__device__ __align__(16) float g_wtd[CIN1*1*COUT];
__device__ __align__(16) float g_stats[3*512];       // per-bn: [2*c]=sum, [2*c+1]=sumsq
__device__ __align__(16) float2 g_aff[3*256];        // per-bn per-channel (scale, shift)

// ---------------- prep: all 3 weight transposes + stats clear in ONE launch ----------------
// w[co][ci][k] -> wt[(ci*KW+k)*COUT + co]
__device__ __forceinline__ void transp(const float* __restrict__ w, float* __restrict__ wt,
                                       int CIN, int KW, int i) {
    int k  = i % KW;
    int ci = (i / KW) % CIN;
    int co = i / (KW * CIN);
    wt[(ci*KW + k)*COUT + co] = w[i];
}

__global__ void prep_kernel(const float* __restrict__ w1, const float* __restrict__ w2,
                            const float* __restrict__ wd,
                            float* __restrict__ wt1, float* __restrict__ wt2,
                            float* __restrict__ wtd, float* __restrict__ stats) {
    int idx = blockIdx.x * 256 + threadIdx.x;
    const int N1 = COUT*CIN1*3;        // 98304
    const int N2 = COUT*COUT*3;        // 196608
    const int ND = COUT*CIN1*1;        // 32768
    if (idx < N1)                     { transp(w1, wt1, CIN1, 3, idx); return; }
    idx -= N1;
    if (idx < N2)                     { transp(w2, wt2, COUT, 3, idx); return; }
    idx -= N2;
    if (idx < ND)                     { transp(wd, wtd, CIN1, 1, idx); return; }
    idx -= ND;
    if (idx < 3*512)                  stats[idx] = 0.0f;
}

__global__ void finalize_bn_kernel(const float* __restrict__ stats,
                                   const float* __restrict__ gamma,
                                   const float* __restrict__ beta,
                                   float2* __restrict__ aff) {
    int c = threadIdx.x;
    if (c < 256) {
        const float inv_n = 1.0f / (float)(BATCH * LLEN);
        float mean = stats[2*c]   * inv_n;
        float var  = stats[2*c+1] * inv_n - mean * mean;
        float sc = gamma[c] * rsqrtf(var + 1e-5f);
        float sh = beta[c] - mean * sc;
        aff[c] = make_float2(sc, sh);
    }
}

// ---------------- LIF (exact arithmetic mirror of the reference) ----------------
__device__ __forceinline__ float lif_mean_f(float c) {
    float v = 0.0f, cnt = 0.0f;
#pragma unroll
    for (int t = 0; t < 8; t++) {
        v = __fmaf_rn(c - v, 0.5f, v);   // == v + (c-v)/2 with reference rounding
        bool spk = (v >= 1.0f);
        cnt += spk ? 1.0f : 0.0f;
        v = spk ? 0.0f : v;
    }
    return cnt * 0.125f;
}

__global__ void lif_kernel(const float4* __restrict__ y, const float2* __restrict__ aff,
                           float4* __restrict__ out) {
    int idx = blockIdx.x * 256 + threadIdx.x;        // NELEM/4 entries
    int c = (idx >> 10) & 255;
    float2 a = aff[c];
    float4 v = y[idx];
    float4 o;
    o.x = lif_mean_f(__fmaf_rn(v.x, a.x, a.y));
    o.y = lif_mean_f(__fmaf_rn(v.y, a.x, a.y));
    o.z = lif_mean_f(__fmaf_rn(v.z, a.x, a.y));
    o.w = lif_mean_f(__fmaf_rn(v.w, a.x, a.y));
    out[idx] = o;
}

__global__ void final_kernel(const float4* __restrict__ y2, const float4* __restrict__ r,
                             const float2* __restrict__ aff2, const float2* __restrict__ affd,
                             float4* __restrict__ out) {
    int idx = blockIdx.x * 256 + threadIdx.x;
    int c = (idx >> 10) & 255;
    float2 a = aff2[c];
    float2 d = affd[c];
    float4 v = y2[idx];
    float4 rv = r[idx];
    float4 o;
    o.x = lif_mean_f(__fmaf_rn(v.x, a.x, a.y)) + __fmaf_rn(rv.x, d.x, d.y);
    o.y = lif_mean_f(__fmaf_rn(v.y, a.x, a.y)) + __fmaf_rn(rv.y, d.x, d.y);
    o.z = lif_mean_f(__fmaf_rn(v.z, a.x, a.y)) + __fmaf_rn(rv.z, d.x, d.y);
    o.w = lif_mean_f(__fmaf_rn(v.w, a.x, a.y)) + __fmaf_rn(rv.w, d.x, d.y);
    out[idx] = o;
}

// ---------------- conv1d ("same" padding) + fused per-channel stats ----------------
// Block: 128 cout x 128 L, one batch. 256 threads; per-thread 8co x 8L as
// 4 co-pair x 8L packed f32x2 accumulators. Double-buffered cp.async staging.
template<int CIN, int KW>
__global__ void __launch_bounds__(256, 2) conv_bn_kernel(
    const float* __restrict__ x, const float* __restrict__ wT,
    const float* __restrict__ bias, float* __restrict__ y,
    float* __restrict__ stats)
{
    constexpr int TL = 128, TCO = 128, CCH = 8;
    constexpr int XW = TL + KW - 1;                 // 130 (K=3) / 128 (K=1)
    constexpr int XS = 136;                         // padded row stride
    constexpr int NC = CIN / CCH;
    __shared__ __align__(16) float xs[2][CCH][XS];
    __shared__ __align__(16) float ws[2][CCH][KW][TCO];

    const int tid = threadIdx.x;
    const int tl  = tid & 15;       // L-group: handles l0 + tl*4 + {0..3} and +64
    const int cot = tid >> 4;       // co-group (8 co each)
    const int l0  = blockIdx.x * TL;
    const int co0 = blockIdx.y * TCO;
    const int b   = blockIdx.z;
    const float* xb = x + (size_t)b * CIN * LLEN;

    unsigned long long accp[4][8];   // [co-pair][L], lo = even co, hi = odd co
#pragma unroll
    for (int i = 0; i < 4; i++)
#pragma unroll
        for (int j = 0; j < 8; j++) accp[i][j] = 0ull;

    // ---- async stager for one ci-chunk into buffer `buf` ----
    auto stage = [&](int buf, int ci0) {
        uint32_t xsa = (uint32_t)__cvta_generic_to_shared(&xs[buf][0][0]);
        for (int i = tid; i < CCH * XW; i += 256) {
            int cl = i / XW, j = i - cl * XW;
            uint32_t dst = xsa + (uint32_t)(cl * XS + j) * 4u;
            if constexpr (KW == 3) {
                int gl = l0 + j - 1;
                int ok = (gl >= 0 && gl < LLEN);
                const float* src = xb + (ci0 + cl) * LLEN + (ok ? gl : 0);
                int sz = ok ? 4 : 0;   // src-size 0 -> zero-fill (sequence padding)
                asm volatile("cp.async.ca.shared.global [%0], [%1], 4, %2;\n"
                             :: "r"(dst), "l"(src), "r"(sz));
            } else {
                const float* src = xb + (ci0 + cl) * LLEN + l0 + j;
                asm volatile("cp.async.ca.shared.global [%0], [%1], 4;\n"
                             :: "r"(dst), "l"(src));
            }
        }
        uint32_t wsa = (uint32_t)__cvta_generic_to_shared(&ws[buf][0][0][0]);
        constexpr int NW16 = CCH * KW * TCO / 4;
        for (int i = tid; i < NW16; i += 256) {
            int col4 = i & 31;
            int k    = (i >> 5) % KW;
            int cl   = i / (32 * KW);
            uint32_t dst = wsa + (uint32_t)(((cl * KW + k) * TCO) + col4 * 4) * 4u;
            const float* src = wT + ((size_t)(ci0 + cl) * KW + k) * COUT + co0 + col4 * 4;
            asm volatile("cp.async.cg.shared.global [%0], [%1], 16;\n"
                         :: "r"(dst), "l"(src));
        }
        asm volatile("cp.async.commit_group;\n");
    };

    stage(0, 0);
    int buf = 0;
    for (int c = 0; c < NC; c++) {
        if (c + 1 < NC) {
            stage(buf ^ 1, (c + 1) * CCH);
            asm volatile("cp.async.wait_group 1;\n");
        } else {
            asm volatile("cp.async.wait_group 0;\n");
        }
        __syncthreads();

#pragma unroll
        for (int cl = 0; cl < CCH; cl++) {
            // weights: consecutive-co pairs come pre-packed from LDS.128
            unsigned long long wp[KW][4];
#pragma unroll
            for (int k = 0; k < KW; k++) {
                ulonglong2 wA = *reinterpret_cast<const ulonglong2*>(&ws[buf][cl][k][cot * 8]);
                ulonglong2 wB = *reinterpret_cast<const ulonglong2*>(&ws[buf][cl][k][cot * 8 + 4]);
                wp[k][0] = wA.x; wp[k][1] = wA.y; wp[k][2] = wB.x; wp[k][3] = wB.y;
            }
#pragma unroll
            for (int h = 0; h < 2; h++) {       // two 4-wide L sub-chunks (16B lane stride)
                const float* xrow = &xs[buf][cl][h * 64 + tl * 4];
                float xv[KW + 3];
                float4 x4 = *reinterpret_cast<const float4*>(xrow);
                xv[0] = x4.x; xv[1] = x4.y; xv[2] = x4.z; xv[3] = x4.w;
                if constexpr (KW == 3) { xv[4] = xrow[4]; xv[5] = xrow[5]; }
                unsigned long long xp[KW + 3];
#pragma unroll
                for (int j = 0; j < KW + 3; j++) PACK2(xp[j], xv[j], xv[j]);
#pragma unroll
                for (int k = 0; k < KW; k++)
#pragma unroll
                    for (int i = 0; i < 4; i++)
#pragma unroll
                        for (int j = 0; j < 4; j++)
                            FMA2(accp[i][h * 4 + j], wp[k][i], xp[j + k], accp[i][h * 4 + j]);
            }
        }
        __syncthreads();
        buf ^= 1;
    }

    // epilogue: unpack, bias, store, per-channel sum/sumsq reduction
#pragma unroll
    for (int p = 0; p < 4; p++) {
        float a0[8], a1[8];
#pragma unroll
        for (int j = 0; j < 8; j++) UNPACK2(a0[j], a1[j], accp[p][j]);
#pragma unroll
        for (int e = 0; e < 2; e++) {
            float* a = e ? a1 : a0;
            int co = co0 + cot * 8 + 2 * p + e;
            float bv = bias[co];
            float s = 0.0f, q = 0.0f;
#pragma unroll
            for (int j = 0; j < 8; j++) {
                a[j] += bv;
                s += a[j];
                q = __fmaf_rn(a[j], a[j], q);
            }
            float* yrow = &y[((size_t)b * COUT + co) * LLEN + l0 + tl * 4];
            *reinterpret_cast<float4*>(yrow)      = make_float4(a[0], a[1], a[2], a[3]);
            *reinterpret_cast<float4*>(yrow + 64) = make_float4(a[4], a[5], a[6], a[7]);
#pragma unroll
            for (int off = 8; off; off >>= 1) {
                s += __shfl_down_sync(0xffffffffu, s, off, 16);
                q += __shfl_down_sync(0xffffffffu, q, off, 16);
            }
            if (tl == 0) {
                atomicAdd(&stats[2 * co],     s);
                atomicAdd(&stats[2 * co + 1], q);
            }
        }
    }
}

// ---------------- launch ----------------
extern "C" void kernel_launch(void* const* d_in, const int* in_sizes, int n_in,
                              void* d_out, int out_size) {
    const float* x   = (const float*)d_in[0];
    const float* w1  = (const float*)d_in[1];
    const float* b1  = (const float*)d_in[2];
    const float* g1  = (const float*)d_in[3];
    const float* be1 = (const float*)d_in[4];
    const float* w2  = (const float*)d_in[5];
    const float* b2  = (const float*)d_in[6];
    const float* g2  = (const float*)d_in[7];
    const float* be2 = (const float*)d_in[8];
    const float* wd  = (const float*)d_in[9];
    const float* bd  = (const float*)d_in[10];
    const float* gd  = (const float*)d_in[11];
    const float* bed = (const float*)d_in[12];
    float* out = (float*)d_out;
    (void)in_sizes; (void)n_in; (void)out_size;   // T = 8 (hardcoded, shapes fixed)

    float *y1, *s1, *y2, *r, *wt1, *wt2, *wtd, *stats;
    float2* aff;
    cudaGetSymbolAddress((void**)&y1,  g_y1);
    cudaGetSymbolAddress((void**)&s1,  g_s1);
    cudaGetSymbolAddress((void**)&y2,  g_y2);
    cudaGetSymbolAddress((void**)&r,   g_r);
    cudaGetSymbolAddress((void**)&wt1, g_wt1);
    cudaGetSymbolAddress((void**)&wt2, g_wt2);
    cudaGetSymbolAddress((void**)&wtd, g_wtd);
    cudaGetSymbolAddress((void**)&stats, g_stats);
    cudaGetSymbolAddress((void**)&aff, g_aff);

    // prep: 98304 + 196608 + 32768 + 1536 = 329216 items
    prep_kernel<<<(329216 + 255)/256, 256>>>(w1, w2, wd, wt1, wt2, wtd, stats);

    dim3 cgrid(LLEN/128, COUT/128, BATCH);
    conv_bn_kernel<CIN1, 3><<<cgrid, 256>>>(x, wt1, b1, y1, stats);            // (1)
    conv_bn_kernel<CIN1, 1><<<cgrid, 256>>>(x, wtd, bd, r,  stats + 1024);     // (2)
    finalize_bn_kernel<<<1, 256>>>(stats,        g1, be1, aff);                // (3) bn1
    finalize_bn_kernel<<<1, 256>>>(stats + 1024, gd, bed, aff + 512);          // (4) bnd
    lif_kernel<<<NELEM/1024, 256>>>((const float4*)y1, aff, (float4*)s1);      // (5)
    conv_bn_kernel<COUT, 3><<<cgrid, 256>>>(s1, wt2, b2, y2, stats + 512);     // (6)
    finalize_bn_kernel<<<1, 256>>>(stats + 512, g2, be2, aff + 256);           // (7) bn2
    final_kernel<<<NELEM/1024, 256>>>((const float4*)y2, (const float4*)r,
                                      aff + 256, aff + 512, (float4*)out);     // (8)
}

// round 14
// speedup vs baseline: 2.6934x; 1.6369x over previous
#include <cuda_runtime.h>
#include <cuda_bf16.h>
#include <cstdint>

#define LLEN 4096
#define BATCH 32
#define COUT 256
#define CIN1 128
#define NELEM (BATCH*COUT*LLEN)   // 33554432

// ---- packed f32x2 helpers (Blackwell FFMA2 path, PTX-only) ----
#define PACK2(out, lo, hi)  asm("mov.b64 %0, {%1, %2};" : "=l"(out) : "f"(lo), "f"(hi))
#define UNPACK2(lo, hi, in) asm("mov.b64 {%0, %1}, %2;" : "=f"(lo), "=f"(hi) : "l"(in))
#define FMA2(d, a, b, c)    asm("fma.rn.f32x2 %0, %1, %2, %3;" : "=l"(d) : "l"(a), "l"(b), "l"(c))

// ---- warp-level tensor ops (baseline PTX, works on plain sm_103 target) ----
#define LDSM_X4(r0, r1, r2, r3, addr) \
    asm volatile("ldmatrix.sync.aligned.m8n8.x4.shared.b16 {%0,%1,%2,%3}, [%4];" \
                 : "=r"(r0), "=r"(r1), "=r"(r2), "=r"(r3) : "r"(addr))
#define MMA16816(d, a, b) \
    asm volatile("mma.sync.aligned.m16n8k16.row.col.f32.bf16.bf16.f32 " \
                 "{%0,%1,%2,%3},{%4,%5,%6,%7},{%8,%9},{%0,%1,%2,%3};" \
                 : "+f"((d)[0]), "+f"((d)[1]), "+f"((d)[2]), "+f"((d)[3]) \
                 : "r"((a)[0]), "r"((a)[1]), "r"((a)[2]), "r"((a)[3]), \
                   "r"((b)[0]), "r"((b)[1]))

// ---------------- scratch (device globals; no allocation allowed) ----------------
__device__ __align__(16) float g_y1[NELEM];                    // conv1 output (fp32)
__device__ __align__(16) float g_y2[NELEM];                    // conv2 output (fp32)
__device__ __align__(16) float g_r [NELEM];                    // ds conv output
__device__ __align__(16) __nv_bfloat16 g_s1T[NELEM];           // lif1 out, channel-major [b][l][ci] bf16
__device__ __align__(16) __nv_bfloat16 g_A2[2*3*COUT*COUT];    // conv2 weights hi/lo: [h][k][co][ci]
__device__ __align__(16) float g_wt1[CIN1*3*COUT];             // transposed fp32 weights [ci][k][co]
__device__ __align__(16) float g_wtd[CIN1*1*COUT];
__device__ __align__(16) float g_stats[3*512];                 // per-bn: sum, sumsq
__device__ __align__(16) float2 g_aff[3*256];                  // per-bn per-channel (scale, shift)

// ---------------- prep: weight transposes + bf16 hi/lo split + stats clear ----------------
__device__ __forceinline__ void transp(const float* __restrict__ w, float* __restrict__ wt,
                                       int CIN, int KW, int i) {
    int k  = i % KW;
    int ci = (i / KW) % CIN;
    int co = i / (KW * CIN);
    wt[(ci*KW + k)*COUT + co] = w[i];
}

__global__ void prep_kernel(const float* __restrict__ w1, const float* __restrict__ w2,
                            const float* __restrict__ wd,
                            float* __restrict__ wt1, float* __restrict__ wtd,
                            __nv_bfloat16* __restrict__ A2, float* __restrict__ stats) {
    int idx = blockIdx.x * 256 + threadIdx.x;
    const int N1 = COUT*CIN1*3;        // 98304
    const int ND = COUT*CIN1*1;        // 32768
    const int NA = COUT*COUT*3;        // 196608
    if (idx < N1) { transp(w1, wt1, CIN1, 3, idx); return; }
    idx -= N1;
    if (idx < ND) { transp(wd, wtd, CIN1, 1, idx); return; }
    idx -= ND;
    if (idx < NA) {
        // w2 layout [co][ci][k]
        int k  = idx % 3;
        int ci = (idx / 3) & 255;
        int co = idx / 768;
        float w = w2[idx];
        __nv_bfloat16 hi = __float2bfloat16(w);
        __nv_bfloat16 lo = __float2bfloat16(w - __bfloat162float(hi));
        A2[(k*COUT + co)*COUT + ci]      = hi;
        A2[NA + (k*COUT + co)*COUT + ci] = lo;
        return;
    }
    idx -= NA;
    if (idx < 3*512) stats[idx] = 0.0f;
}

__global__ void finalize_bn_kernel(const float* __restrict__ stats,
                                   const float* __restrict__ gamma,
                                   const float* __restrict__ beta,
                                   float2* __restrict__ aff) {
    int c = threadIdx.x;
    if (c < 256) {
        const float inv_n = 1.0f / (float)(BATCH * LLEN);
        float mean = stats[2*c]   * inv_n;
        float var  = stats[2*c+1] * inv_n - mean * mean;
        float sc = gamma[c] * rsqrtf(var + 1e-5f);
        float sh = beta[c] - mean * sc;
        aff[c] = make_float2(sc, sh);
    }
}

// ---------------- LIF (exact arithmetic mirror of the reference) ----------------
__device__ __forceinline__ float lif_mean_f(float c) {
    float v = 0.0f, cnt = 0.0f;
#pragma unroll
    for (int t = 0; t < 8; t++) {
        v = __fmaf_rn(c - v, 0.5f, v);   // == v + (c-v)/2 with reference rounding
        bool spk = (v >= 1.0f);
        cnt += spk ? 1.0f : 0.0f;
        v = spk ? 0.0f : v;
    }
    return cnt * 0.125f;                 // multiple of 1/8: EXACT in bf16
}

// LIF stage 1 + transpose to channel-major bf16: s1T[b][l][c]
__global__ void __launch_bounds__(256) lif_t_kernel(const float4* __restrict__ y,
                                                    const float2* __restrict__ aff,
                                                    __nv_bfloat16* __restrict__ s1T) {
    __shared__ __nv_bfloat16 sm[64][72];   // [l][c], stride 72 elems = 144B (16B aligned)
    const int l0 = blockIdx.x * 64, c0 = blockIdx.y * 64, b = blockIdx.z;
    const int tid = threadIdx.x;
    const int lq = tid & 15;
    const int cl = tid >> 4;
#pragma unroll
    for (int p = 0; p < 4; p++) {
        int c = c0 + p * 16 + cl;
        float2 a = aff[c];
        float4 v = y[((size_t)b * 256 + c) * 1024 + (l0 >> 2) + lq];
        sm[lq*4+0][p*16+cl] = __float2bfloat16(lif_mean_f(__fmaf_rn(v.x, a.x, a.y)));
        sm[lq*4+1][p*16+cl] = __float2bfloat16(lif_mean_f(__fmaf_rn(v.y, a.x, a.y)));
        sm[lq*4+2][p*16+cl] = __float2bfloat16(lif_mean_f(__fmaf_rn(v.z, a.x, a.y)));
        sm[lq*4+3][p*16+cl] = __float2bfloat16(lif_mean_f(__fmaf_rn(v.w, a.x, a.y)));
    }
    __syncthreads();
    // each thread copies its full 16-element segment (2 x uint4 = 32B)  [round-12 fix]
    int r = tid >> 2, seg = tid & 3;
    uint4 u0 = *reinterpret_cast<const uint4*>(&sm[r][seg*16]);      // elems +0..7
    uint4 u1 = *reinterpret_cast<const uint4*>(&sm[r][seg*16 + 8]);  // elems +8..15
    __nv_bfloat16* drow = s1T + ((size_t)b * LLEN + l0 + r) * 256 + c0;
    *reinterpret_cast<uint4*>(drow + seg*16)     = u0;
    *reinterpret_cast<uint4*>(drow + seg*16 + 8) = u1;
}

__global__ void final_kernel(const float4* __restrict__ y2, const float4* __restrict__ r,
                             const float2* __restrict__ aff2, const float2* __restrict__ affd,
                             float4* __restrict__ out) {
    int idx = blockIdx.x * 256 + threadIdx.x;
    int c = (idx >> 10) & 255;
    float2 a = aff2[c];
    float2 d = affd[c];
    float4 v = y2[idx];
    float4 rv = r[idx];
    float4 o;
    o.x = lif_mean_f(__fmaf_rn(v.x, a.x, a.y)) + __fmaf_rn(rv.x, d.x, d.y);
    o.y = lif_mean_f(__fmaf_rn(v.y, a.x, a.y)) + __fmaf_rn(rv.y, d.x, d.y);
    o.z = lif_mean_f(__fmaf_rn(v.z, a.x, a.y)) + __fmaf_rn(rv.z, d.x, d.y);
    o.w = lif_mean_f(__fmaf_rn(v.w, a.x, a.y)) + __fmaf_rn(rv.w, d.x, d.y);
    out[idx] = o;
}

// ---------------- conv1/ds: FFMA2 path (unchanged from best kernel) ----------------
template<int CIN, int KW>
__global__ void __launch_bounds__(256, 2) conv_bn_kernel(
    const float* __restrict__ x, const float* __restrict__ wT,
    const float* __restrict__ bias, float* __restrict__ y,
    float* __restrict__ stats)
{
    constexpr int TL = 128, TCO = 128, CCH = 8;
    constexpr int XW = TL + KW - 1;
    constexpr int XS = 136;
    constexpr int NC = CIN / CCH;
    __shared__ __align__(16) float xs[2][CCH][XS];
    __shared__ __align__(16) float ws[2][CCH][KW][TCO];

    const int tid = threadIdx.x;
    const int tl  = tid & 15;
    const int cot = tid >> 4;
    const int l0  = blockIdx.x * TL;
    const int co0 = blockIdx.y * TCO;
    const int b   = blockIdx.z;
    const float* xb = x + (size_t)b * CIN * LLEN;

    unsigned long long accp[4][8];
#pragma unroll
    for (int i = 0; i < 4; i++)
#pragma unroll
        for (int j = 0; j < 8; j++) accp[i][j] = 0ull;

    auto stage = [&](int buf, int ci0) {
        uint32_t xsa = (uint32_t)__cvta_generic_to_shared(&xs[buf][0][0]);
        for (int i = tid; i < CCH * XW; i += 256) {
            int cl = i / XW, j = i - cl * XW;
            uint32_t dst = xsa + (uint32_t)(cl * XS + j) * 4u;
            if constexpr (KW == 3) {
                int gl = l0 + j - 1;
                int ok = (gl >= 0 && gl < LLEN);
                const float* src = xb + (ci0 + cl) * LLEN + (ok ? gl : 0);
                int sz = ok ? 4 : 0;
                asm volatile("cp.async.ca.shared.global [%0], [%1], 4, %2;\n"
                             :: "r"(dst), "l"(src), "r"(sz));
            } else {
                const float* src = xb + (ci0 + cl) * LLEN + l0 + j;
                asm volatile("cp.async.ca.shared.global [%0], [%1], 4;\n"
                             :: "r"(dst), "l"(src));
            }
        }
        uint32_t wsa = (uint32_t)__cvta_generic_to_shared(&ws[buf][0][0][0]);
        constexpr int NW16 = CCH * KW * TCO / 4;
        for (int i = tid; i < NW16; i += 256) {
            int col4 = i & 31;
            int k    = (i >> 5) % KW;
            int cl   = i / (32 * KW);
            uint32_t dst = wsa + (uint32_t)(((cl * KW + k) * TCO) + col4 * 4) * 4u;
            const float* src = wT + ((size_t)(ci0 + cl) * KW + k) * COUT + co0 + col4 * 4;
            asm volatile("cp.async.cg.shared.global [%0], [%1], 16;\n"
                         :: "r"(dst), "l"(src));
        }
        asm volatile("cp.async.commit_group;\n");
    };

    stage(0, 0);
    int buf = 0;
    for (int c = 0; c < NC; c++) {
        if (c + 1 < NC) {
            stage(buf ^ 1, (c + 1) * CCH);
            asm volatile("cp.async.wait_group 1;\n");
        } else {
            asm volatile("cp.async.wait_group 0;\n");
        }
        __syncthreads();

#pragma unroll
        for (int cl = 0; cl < CCH; cl++) {
            unsigned long long wp[KW][4];
#pragma unroll
            for (int k = 0; k < KW; k++) {
                ulonglong2 wA = *reinterpret_cast<const ulonglong2*>(&ws[buf][cl][k][cot * 8]);
                ulonglong2 wB = *reinterpret_cast<const ulonglong2*>(&ws[buf][cl][k][cot * 8 + 4]);
                wp[k][0] = wA.x; wp[k][1] = wA.y; wp[k][2] = wB.x; wp[k][3] = wB.y;
            }
#pragma unroll
            for (int h = 0; h < 2; h++) {
                const float* xrow = &xs[buf][cl][h * 64 + tl * 4];
                float xv[KW + 3];
                float4 x4 = *reinterpret_cast<const float4*>(xrow);
                xv[0] = x4.x; xv[1] = x4.y; xv[2] = x4.z; xv[3] = x4.w;
                if constexpr (KW == 3) { xv[4] = xrow[4]; xv[5] = xrow[5]; }
                unsigned long long xp[KW + 3];
#pragma unroll
                for (int j = 0; j < KW + 3; j++) PACK2(xp[j], xv[j], xv[j]);
#pragma unroll
                for (int k = 0; k < KW; k++)
#pragma unroll
                    for (int i = 0; i < 4; i++)
#pragma unroll
                        for (int j = 0; j < 4; j++)
                            FMA2(accp[i][h * 4 + j], wp[k][i], xp[j + k], accp[i][h * 4 + j]);
            }
        }
        __syncthreads();
        buf ^= 1;
    }

#pragma unroll
    for (int p = 0; p < 4; p++) {
        float a0[8], a1[8];
#pragma unroll
        for (int j = 0; j < 8; j++) UNPACK2(a0[j], a1[j], accp[p][j]);
#pragma unroll
        for (int e = 0; e < 2; e++) {
            float* a = e ? a1 : a0;
            int co = co0 + cot * 8 + 2 * p + e;
            float bv = bias[co];
            float s = 0.0f, q = 0.0f;
#pragma unroll
            for (int j = 0; j < 8; j++) {
                a[j] += bv;
                s += a[j];
                q = __fmaf_rn(a[j], a[j], q);
            }
            float* yrow = &y[((size_t)b * COUT + co) * LLEN + l0 + tl * 4];
            *reinterpret_cast<float4*>(yrow)      = make_float4(a[0], a[1], a[2], a[3]);
            *reinterpret_cast<float4*>(yrow + 64) = make_float4(a[4], a[5], a[6], a[7]);
#pragma unroll
            for (int off = 8; off; off >>= 1) {
                s += __shfl_down_sync(0xffffffffu, s, off, 16);
                q += __shfl_down_sync(0xffffffffu, q, off, 16);
            }
            if (tl == 0) {
                atomicAdd(&stats[2 * co],     s);
                atomicAdd(&stats[2 * co + 1], q);
            }
        }
    }
}

// ============== conv2 via warp-level mma.sync bf16 (split-weight fp32 emulation) ==============
// Per CTA: D[128 co, 128 l] = sum over K'=(k outer, ci inner)=768 of A[co,K']·B[l,K'].
// A = w2 hi/lo bf16 K-major (128B rows, 16B-chunk XOR swizzle). B rows = s1T[b, l+k-1, ci chunk].
// 8 warps as 2(co) x 4(l); warp tile 64 co x 32 l; m16n8k16; fp32 accum; hi+lo passes.

#define C2_STAGE 49152u    // A hi 16K + A lo 16K + B 16K
#define C2_SMEM  98304

__global__ void __launch_bounds__(256) conv2_mma_kernel(
    const __nv_bfloat16* __restrict__ s1T, const __nv_bfloat16* __restrict__ A2,
    const float* __restrict__ bias, float* __restrict__ y, float* __restrict__ stats)
{
    extern __shared__ __align__(128) char smem[];
    uint32_t sbase = (uint32_t)__cvta_generic_to_shared(smem);
    const int tid  = threadIdx.x;
    const int lane = tid & 31;
    const int w    = tid >> 5;
    const int wm   = w & 1;          // co half (64 each)
    const int wn   = w >> 1;         // l quarter (32 each)
    const int l0   = blockIdx.x * 128;
    const int co0  = blockIdx.y * 128;
    const int bb   = blockIdx.z;
    const int NA   = COUT * COUT * 3;
    const int NC   = 12;             // 3 k x 4 ci-chunks of 64

    float acc[4][4][4];              // [mt][nt][frag]
#pragma unroll
    for (int i = 0; i < 4; i++)
#pragma unroll
        for (int j = 0; j < 4; j++)
#pragma unroll
            for (int e = 0; e < 4; e++) acc[i][j][e] = 0.0f;

    // --- stage one K-chunk (fixed k, 64 ci) into buffer st ---
    auto stagec = [&](int st, int c) {
        int k = c >> 2, ci0 = (c & 3) << 6;
        uint32_t base = sbase + (uint32_t)st * C2_STAGE;
        // A hi/lo: 2 x 128 rows x 8 chunks of 16B
        for (int i = tid; i < 2048; i += 256) {
            int h = i >> 10, r = (i >> 3) & 127, j = i & 7;
            uint32_t dst = base + (uint32_t)h * 16384u + (uint32_t)r * 128u
                         + (uint32_t)((j ^ (r & 7)) << 4);
            const __nv_bfloat16* src = A2 + (size_t)h * NA
                                     + ((k * COUT + co0 + r) * COUT) + ci0 + (j << 3);
            asm volatile("cp.async.cg.shared.global [%0], [%1], 16;\n" :: "r"(dst), "l"(src));
        }
        // B: 128 l-rows x 8 chunks, row r -> l = l0 + r + k - 1 (zero-fill OOB)
        for (int i = tid; i < 1024; i += 256) {
            int r = (i >> 3) & 127, j = i & 7;
            int l = l0 + r + k - 1;
            int ok = (l >= 0 && l < LLEN);
            uint32_t dst = base + 32768u + (uint32_t)r * 128u
                         + (uint32_t)((j ^ (r & 7)) << 4);
            const __nv_bfloat16* src = s1T + (((size_t)bb << 12) + (ok ? l : 0)) * 256
                                     + ci0 + (j << 3);
            int sz = ok ? 16 : 0;
            asm volatile("cp.async.cg.shared.global [%0], [%1], 16, %2;\n"
                         :: "r"(dst), "l"(src), "r"(sz));
        }
        asm volatile("cp.async.commit_group;\n");
    };

    stagec(0, 0);
    stagec(1, 1);
    for (int c = 0; c < NC; c++) {
        int st = c & 1;
        if (c + 2 < NC) asm volatile("cp.async.wait_group 1;\n");
        else            asm volatile("cp.async.wait_group 0;\n");
        __syncthreads();

        uint32_t base = sbase + (uint32_t)st * C2_STAGE;
        // lane address roles
        int arow = wm * 64 + (lane & 15);              // + mt*16
        int browp = ((lane >> 4) << 3) + (lane & 7);   // row within nt-pair (0..15)
        int bchl = (lane >> 3) & 1;                    // chunk low bit for B
#pragma unroll
        for (int ks = 0; ks < 4; ks++) {
            // B frags: 2 x ldmatrix.x4 -> 4 n-tiles (n-major [l][ci] == col-major KxN)
            uint32_t bfr[4][2];
#pragma unroll
            for (int p = 0; p < 2; p++) {
                int row = wn * 32 + p * 16 + browp;
                int ch  = ks * 2 + bchl;
                uint32_t addr = base + 32768u + (uint32_t)row * 128u
                              + (uint32_t)((ch ^ (row & 7)) << 4);
                uint32_t t0, t1, t2, t3;
                LDSM_X4(t0, t1, t2, t3, addr);
                bfr[2*p][0] = t0; bfr[2*p][1] = t1;
                bfr[2*p+1][0] = t2; bfr[2*p+1][1] = t3;
            }
#pragma unroll
            for (int h = 0; h < 2; h++) {
                uint32_t ab = base + (uint32_t)h * 16384u;
                uint32_t afr[4][4];
#pragma unroll
                for (int mt = 0; mt < 4; mt++) {
                    int row = arow + mt * 16;
                    int ch  = ks * 2 + (lane >> 4);
                    uint32_t addr = ab + (uint32_t)row * 128u
                                  + (uint32_t)((ch ^ (row & 7)) << 4);
                    LDSM_X4(afr[mt][0], afr[mt][1], afr[mt][2], afr[mt][3], addr);
                }
#pragma unroll
                for (int mt = 0; mt < 4; mt++)
#pragma unroll
                    for (int nt = 0; nt < 4; nt++)
                        MMA16816(acc[mt][nt], afr[mt], bfr[nt]);
            }
        }
        __syncthreads();
        if (c + 2 < NC) stagec(st, c + 2);
    }

    // --- epilogue: bias + store + per-channel stats ---
    const int gid = lane >> 2, tig = lane & 3;
#pragma unroll
    for (int mt = 0; mt < 4; mt++) {
        int r0 = co0 + wm * 64 + mt * 16 + gid;
        int r1 = r0 + 8;
        float bv0 = bias[r0], bv1 = bias[r1];
        float s0 = 0.0f, q0 = 0.0f, s1 = 0.0f, q1 = 0.0f;
#pragma unroll
        for (int nt = 0; nt < 4; nt++) {
            int l = l0 + wn * 32 + nt * 8 + tig * 2;
            float d0 = acc[mt][nt][0] + bv0, d1 = acc[mt][nt][1] + bv0;
            float d2 = acc[mt][nt][2] + bv1, d3 = acc[mt][nt][3] + bv1;
            *reinterpret_cast<float2*>(&y[((size_t)bb * COUT + r0) * LLEN + l]) = make_float2(d0, d1);
            *reinterpret_cast<float2*>(&y[((size_t)bb * COUT + r1) * LLEN + l]) = make_float2(d2, d3);
            s0 += d0 + d1; q0 = __fmaf_rn(d0, d0, q0); q0 = __fmaf_rn(d1, d1, q0);
            s1 += d2 + d3; q1 = __fmaf_rn(d2, d2, q1); q1 = __fmaf_rn(d3, d3, q1);
        }
#pragma unroll
        for (int off = 1; off < 4; off <<= 1) {
            s0 += __shfl_xor_sync(0xffffffffu, s0, off, 4);
            q0 += __shfl_xor_sync(0xffffffffu, q0, off, 4);
            s1 += __shfl_xor_sync(0xffffffffu, s1, off, 4);
            q1 += __shfl_xor_sync(0xffffffffu, q1, off, 4);
        }
        if (tig == 0) {
            atomicAdd(&stats[2 * r0],     s0);
            atomicAdd(&stats[2 * r0 + 1], q0);
            atomicAdd(&stats[2 * r1],     s1);
            atomicAdd(&stats[2 * r1 + 1], q1);
        }
    }
}

// ---------------- launch ----------------
extern "C" void kernel_launch(void* const* d_in, const int* in_sizes, int n_in,
                              void* d_out, int out_size) {
    const float* x   = (const float*)d_in[0];
    const float* w1  = (const float*)d_in[1];
    const float* b1  = (const float*)d_in[2];
    const float* g1  = (const float*)d_in[3];
    const float* be1 = (const float*)d_in[4];
    const float* w2  = (const float*)d_in[5];
    const float* b2  = (const float*)d_in[6];
    const float* g2  = (const float*)d_in[7];
    const float* be2 = (const float*)d_in[8];
    const float* wd  = (const float*)d_in[9];
    const float* bd  = (const float*)d_in[10];
    const float* gd  = (const float*)d_in[11];
    const float* bed = (const float*)d_in[12];
    float* out = (float*)d_out;
    (void)in_sizes; (void)n_in; (void)out_size;   // T = 8 (hardcoded, shapes fixed)

    float *y1, *y2, *r, *wt1, *wtd, *stats;
    __nv_bfloat16 *s1T, *A2;
    float2* aff;
    cudaGetSymbolAddress((void**)&y1,  g_y1);
    cudaGetSymbolAddress((void**)&y2,  g_y2);
    cudaGetSymbolAddress((void**)&r,   g_r);
    cudaGetSymbolAddress((void**)&s1T, g_s1T);
    cudaGetSymbolAddress((void**)&A2,  g_A2);
    cudaGetSymbolAddress((void**)&wt1, g_wt1);
    cudaGetSymbolAddress((void**)&wtd, g_wtd);
    cudaGetSymbolAddress((void**)&stats, g_stats);
    cudaGetSymbolAddress((void**)&aff, g_aff);

    cudaFuncSetAttribute(conv2_mma_kernel,
                         cudaFuncAttributeMaxDynamicSharedMemorySize, C2_SMEM);

    // prep: 98304 + 32768 + 196608 + 1536 = 329216 items
    prep_kernel<<<(329216 + 255)/256, 256>>>(w1, w2, wd, wt1, wtd, A2, stats);

    dim3 cgrid(LLEN/128, COUT/128, BATCH);
    conv_bn_kernel<CIN1, 3><<<cgrid, 256>>>(x, wt1, b1, y1, stats);            // conv1
    conv_bn_kernel<CIN1, 1><<<cgrid, 256>>>(x, wtd, bd, r,  stats + 1024);     // ds
    finalize_bn_kernel<<<1, 256>>>(stats,        g1, be1, aff);                // bn1
    finalize_bn_kernel<<<1, 256>>>(stats + 1024, gd, bed, aff + 512);          // bnd
    // LIF stage 1 -> channel-major bf16
    lif_t_kernel<<<dim3(LLEN/64, COUT/64, BATCH), 256>>>((const float4*)y1, aff, s1T);
    // conv2 on tensor cores (warp-level HMMA)
    conv2_mma_kernel<<<dim3(LLEN/128, COUT/128, BATCH), 256, C2_SMEM>>>(
        s1T, A2, b2, y2, stats + 512);
    finalize_bn_kernel<<<1, 256>>>(stats + 512, g2, be2, aff + 256);           // bn2
    final_kernel<<<NELEM/1024, 256>>>((const float4*)y2, (const float4*)r,
                                      aff + 256, aff + 512, (float4*)out);
}

// round 17
// speedup vs baseline: 3.3679x; 1.2504x over previous
#include <cuda_runtime.h>
#include <cuda_bf16.h>
#include <cstdint>

#define LLEN 4096
#define BATCH 32
#define COUT 256
#define CIN1 128
#define NELEM (BATCH*COUT*LLEN)   // 33554432
#define XELEM (BATCH*CIN1*LLEN)   // 16777216

// ---- warp-level tensor ops (baseline PTX, works on plain sm_103 target) ----
#define LDSM_X4(r0, r1, r2, r3, addr) \
    asm volatile("ldmatrix.sync.aligned.m8n8.x4.shared.b16 {%0,%1,%2,%3}, [%4];" \
                 : "=r"(r0), "=r"(r1), "=r"(r2), "=r"(r3) : "r"(addr))
#define MMA16816(d, a, b) \
    asm volatile("mma.sync.aligned.m16n8k16.row.col.f32.bf16.bf16.f32 " \
                 "{%0,%1,%2,%3},{%4,%5,%6,%7},{%8,%9},{%0,%1,%2,%3};" \
                 : "+f"((d)[0]), "+f"((d)[1]), "+f"((d)[2]), "+f"((d)[3]) \
                 : "r"((a)[0]), "r"((a)[1]), "r"((a)[2]), "r"((a)[3]), \
                   "r"((b)[0]), "r"((b)[1]))

// ---------------- scratch (device globals; no allocation allowed) ----------------
__device__ __align__(16) float g_y1[NELEM];                    // conv1 output (fp32)
__device__ __align__(16) float g_y2[NELEM];                    // conv2 output (fp32)
__device__ __align__(16) float g_r [NELEM];                    // ds conv output
__device__ __align__(16) __nv_bfloat16 g_s1T[NELEM];           // lif1 out, [b][l][ci] bf16 (exact)
__device__ __align__(16) __nv_bfloat16 g_xh[XELEM];            // x hi, [b][l][ci] bf16
__device__ __align__(16) __nv_bfloat16 g_xl[XELEM];            // x lo
__device__ __align__(16) __nv_bfloat16 g_A1[2*3*COUT*CIN1];    // conv1 w hi/lo: [h][k][co][ci]
__device__ __align__(16) __nv_bfloat16 g_Ad[2*1*COUT*CIN1];    // ds    w hi/lo
__device__ __align__(16) __nv_bfloat16 g_A2[2*3*COUT*COUT];    // conv2 w hi/lo
__device__ __align__(16) float g_stats[3*512];                 // per-bn: sum, sumsq
__device__ __align__(16) float2 g_aff[3*256];                  // per-bn per-channel (scale, shift)

// ---------------- prep: weight hi/lo splits + stats clear ----------------
__global__ void prep_kernel(const float* __restrict__ w1, const float* __restrict__ w2,
                            const float* __restrict__ wd,
                            __nv_bfloat16* __restrict__ A1, __nv_bfloat16* __restrict__ Ad,
                            __nv_bfloat16* __restrict__ A2, float* __restrict__ stats) {
    int idx = blockIdx.x * 256 + threadIdx.x;
    const int N1 = COUT*CIN1*3;        // 98304
    const int ND = COUT*CIN1*1;        // 32768
    const int NA = COUT*COUT*3;        // 196608
    if (idx < N1) {
        // w1 layout [co][ci][k], Cin=128
        int k  = idx % 3;
        int ci = (idx / 3) & 127;
        int co = idx / 384;
        float w = w1[idx];
        __nv_bfloat16 hi = __float2bfloat16(w);
        __nv_bfloat16 lo = __float2bfloat16(w - __bfloat162float(hi));
        A1[(k*COUT + co)*CIN1 + ci]      = hi;
        A1[N1 + (k*COUT + co)*CIN1 + ci] = lo;
        return;
    }
    idx -= N1;
    if (idx < ND) {
        int ci = idx & 127;
        int co = idx >> 7;
        float w = wd[idx];
        __nv_bfloat16 hi = __float2bfloat16(w);
        __nv_bfloat16 lo = __float2bfloat16(w - __bfloat162float(hi));
        Ad[co*CIN1 + ci]      = hi;
        Ad[ND + co*CIN1 + ci] = lo;
        return;
    }
    idx -= ND;
    if (idx < NA) {
        // w2 layout [co][ci][k], Cin=256
        int k  = idx % 3;
        int ci = (idx / 3) & 255;
        int co = idx / 768;
        float w = w2[idx];
        __nv_bfloat16 hi = __float2bfloat16(w);
        __nv_bfloat16 lo = __float2bfloat16(w - __bfloat162float(hi));
        A2[(k*COUT + co)*COUT + ci]      = hi;
        A2[NA + (k*COUT + co)*COUT + ci] = lo;
        return;
    }
    idx -= NA;
    if (idx < 3*512) stats[idx] = 0.0f;
}

// ---------------- x -> channel-major bf16 hi/lo split: xh/xl[b][l][ci] ----------------
__global__ void __launch_bounds__(256) xsplit_kernel(const float4* __restrict__ x,
                                                     __nv_bfloat16* __restrict__ xh,
                                                     __nv_bfloat16* __restrict__ xl) {
    __shared__ __nv_bfloat16 smh[64][72];   // [l][c], stride 144B (16B aligned)
    __shared__ __nv_bfloat16 sml[64][72];
    const int l0 = blockIdx.x * 64, c0 = blockIdx.y * 64, b = blockIdx.z;
    const int tid = threadIdx.x;
    const int lq = tid & 15;
    const int cl = tid >> 4;
#pragma unroll
    for (int p = 0; p < 4; p++) {
        int c = c0 + p * 16 + cl;
        float4 v = x[((size_t)b * CIN1 + c) * 1024 + (l0 >> 2) + lq];
        float vv[4] = {v.x, v.y, v.z, v.w};
#pragma unroll
        for (int e = 0; e < 4; e++) {
            __nv_bfloat16 hi = __float2bfloat16(vv[e]);
            __nv_bfloat16 lo = __float2bfloat16(vv[e] - __bfloat162float(hi));
            smh[lq*4+e][p*16+cl] = hi;
            sml[lq*4+e][p*16+cl] = lo;
        }
    }
    __syncthreads();
    int r = tid >> 2, seg = tid & 3;
    size_t doff = ((size_t)b * LLEN + l0 + r) * CIN1 + c0 + seg*16;
    {
        uint4 u0 = *reinterpret_cast<const uint4*>(&smh[r][seg*16]);
        uint4 u1 = *reinterpret_cast<const uint4*>(&smh[r][seg*16 + 8]);
        *reinterpret_cast<uint4*>(xh + doff)     = u0;
        *reinterpret_cast<uint4*>(xh + doff + 8) = u1;
    }
    {
        uint4 u0 = *reinterpret_cast<const uint4*>(&sml[r][seg*16]);
        uint4 u1 = *reinterpret_cast<const uint4*>(&sml[r][seg*16 + 8]);
        *reinterpret_cast<uint4*>(xl + doff)     = u0;
        *reinterpret_cast<uint4*>(xl + doff + 8) = u1;
    }
}

__global__ void finalize_bn_kernel(const float* __restrict__ stats,
                                   const float* __restrict__ gamma,
                                   const float* __restrict__ beta,
                                   float2* __restrict__ aff) {
    int c = threadIdx.x;
    if (c < 256) {
        const float inv_n = 1.0f / (float)(BATCH * LLEN);
        float mean = stats[2*c]   * inv_n;
        float var  = stats[2*c+1] * inv_n - mean * mean;
        float sc = gamma[c] * rsqrtf(var + 1e-5f);
        float sh = beta[c] - mean * sc;
        aff[c] = make_float2(sc, sh);
    }
}

// ---------------- LIF (exact arithmetic mirror of the reference) ----------------
__device__ __forceinline__ float lif_mean_f(float c) {
    float v = 0.0f, cnt = 0.0f;
#pragma unroll
    for (int t = 0; t < 8; t++) {
        v = __fmaf_rn(c - v, 0.5f, v);   // == v + (c-v)/2 with reference rounding
        bool spk = (v >= 1.0f);
        cnt += spk ? 1.0f : 0.0f;
        v = spk ? 0.0f : v;
    }
    return cnt * 0.125f;                 // multiple of 1/8: EXACT in bf16
}

// LIF stage 1 + transpose to channel-major bf16: s1T[b][l][c]
__global__ void __launch_bounds__(256) lif_t_kernel(const float4* __restrict__ y,
                                                    const float2* __restrict__ aff,
                                                    __nv_bfloat16* __restrict__ s1T) {
    __shared__ __nv_bfloat16 sm[64][72];
    const int l0 = blockIdx.x * 64, c0 = blockIdx.y * 64, b = blockIdx.z;
    const int tid = threadIdx.x;
    const int lq = tid & 15;
    const int cl = tid >> 4;
#pragma unroll
    for (int p = 0; p < 4; p++) {
        int c = c0 + p * 16 + cl;
        float2 a = aff[c];
        float4 v = y[((size_t)b * 256 + c) * 1024 + (l0 >> 2) + lq];
        sm[lq*4+0][p*16+cl] = __float2bfloat16(lif_mean_f(__fmaf_rn(v.x, a.x, a.y)));
        sm[lq*4+1][p*16+cl] = __float2bfloat16(lif_mean_f(__fmaf_rn(v.y, a.x, a.y)));
        sm[lq*4+2][p*16+cl] = __float2bfloat16(lif_mean_f(__fmaf_rn(v.z, a.x, a.y)));
        sm[lq*4+3][p*16+cl] = __float2bfloat16(lif_mean_f(__fmaf_rn(v.w, a.x, a.y)));
    }
    __syncthreads();
    int r = tid >> 2, seg = tid & 3;
    uint4 u0 = *reinterpret_cast<const uint4*>(&sm[r][seg*16]);
    uint4 u1 = *reinterpret_cast<const uint4*>(&sm[r][seg*16 + 8]);
    __nv_bfloat16* drow = s1T + ((size_t)b * LLEN + l0 + r) * 256 + c0;
    *reinterpret_cast<uint4*>(drow + seg*16)     = u0;
    *reinterpret_cast<uint4*>(drow + seg*16 + 8) = u1;
}

__global__ void final_kernel(const float4* __restrict__ y2, const float4* __restrict__ r,
                             const float2* __restrict__ aff2, const float2* __restrict__ affd,
                             float4* __restrict__ out) {
    int idx = blockIdx.x * 256 + threadIdx.x;
    int c = (idx >> 10) & 255;
    float2 a = aff2[c];
    float2 d = affd[c];
    float4 v = y2[idx];
    float4 rv = r[idx];
    float4 o;
    o.x = lif_mean_f(__fmaf_rn(v.x, a.x, a.y)) + __fmaf_rn(rv.x, d.x, d.y);
    o.y = lif_mean_f(__fmaf_rn(v.y, a.x, a.y)) + __fmaf_rn(rv.y, d.x, d.y);
    o.z = lif_mean_f(__fmaf_rn(v.z, a.x, a.y)) + __fmaf_rn(rv.z, d.x, d.y);
    o.w = lif_mean_f(__fmaf_rn(v.w, a.x, a.y)) + __fmaf_rn(rv.w, d.x, d.y);
    out[idx] = o;
}

// ============== unified conv via warp-level mma.sync bf16 ==============
// D[128 co, 128 l] = sum over K'=(k outer, ci inner)=KW*CIN_ of A[co,K']·B[l,K'].
// TERMS=4: Ah·Bh + Ah·Bl + Al·Bh + Al·Bl (full dbf16 product; feeds LIF -> needs fp32-class)
// TERMS=3: Ah·Bh + Ah·Bl + Al·Bh        (linear path; ~1e-5 fine)
// TERMS=2: Ah·B  + Al·B                  (B exact in bf16, spike path)
// 8 warps as 2(co) x 4(l); warp tile 64x32; m16n8k16; fp32 accum; double-buffered cp.async.

template<int KW, int CIN_, int TERMS>
__global__ void __launch_bounds__(256) conv_mma_kernel(
    const __nv_bfloat16* __restrict__ Bhi, const __nv_bfloat16* __restrict__ Blo,
    const __nv_bfloat16* __restrict__ A,
    const float* __restrict__ bias, float* __restrict__ y, float* __restrict__ stats)
{
    constexpr bool BSPLIT = (TERMS >= 3);
    extern __shared__ __align__(128) char smem[];
    uint32_t sbase = (uint32_t)__cvta_generic_to_shared(smem);
    const int tid  = threadIdx.x;
    const int lane = tid & 31;
    const int w    = tid >> 5;
    const int wm   = w & 1;          // co half (64 each)
    const int wn   = w >> 1;         // l quarter (32 each)
    const int l0   = blockIdx.x * 128;
    const int co0  = blockIdx.y * 128;
    const int bb   = blockIdx.z;
    constexpr int NCI = CIN_ / 64;
    constexpr int NC  = KW * NCI;
    constexpr int PAD = KW / 2;
    constexpr uint32_t CSTAGE = BSPLIT ? 65536u : 49152u;
    const size_t AHALF = (size_t)KW * COUT * CIN_;

    float acc[4][4][4];
#pragma unroll
    for (int i = 0; i < 4; i++)
#pragma unroll
        for (int j = 0; j < 4; j++)
#pragma unroll
            for (int e = 0; e < 4; e++) acc[i][j][e] = 0.0f;

    // --- stage one K-chunk (fixed k, 64 ci) into buffer st ---
    auto stagec = [&](int st, int c) {
        int k = c / NCI, ci0 = (c % NCI) * 64;
        uint32_t base = sbase + (uint32_t)st * CSTAGE;
        // A hi/lo: 2 x 128 rows x 8 chunks of 16B
        for (int i = tid; i < 2048; i += 256) {
            int h = i >> 10, r = (i >> 3) & 127, j = i & 7;
            uint32_t dst = base + (uint32_t)h * 16384u + (uint32_t)r * 128u
                         + (uint32_t)((j ^ (r & 7)) << 4);
            const __nv_bfloat16* src = A + (size_t)h * AHALF
                                     + ((size_t)(k * COUT + co0 + r)) * CIN_ + ci0 + (j << 3);
            asm volatile("cp.async.cg.shared.global [%0], [%1], 16;\n" :: "r"(dst), "l"(src));
        }
        // B (hi, and lo if split): row r -> l = l0 + r + k - PAD (zero-fill OOB)
        constexpr int NB = BSPLIT ? 2048 : 1024;
        for (int i = tid; i < NB; i += 256) {
            int h = i >> 10, r = (i >> 3) & 127, j = i & 7;
            int l = l0 + r + k - PAD;
            int ok = (l >= 0 && l < LLEN);
            uint32_t dst = base + 32768u + (uint32_t)h * 16384u + (uint32_t)r * 128u
                         + (uint32_t)((j ^ (r & 7)) << 4);
            const __nv_bfloat16* bp = h ? Blo : Bhi;
            const __nv_bfloat16* src = bp + ((size_t)bb * LLEN + (ok ? l : 0)) * CIN_
                                     + ci0 + (j << 3);
            int sz = ok ? 16 : 0;
            asm volatile("cp.async.cg.shared.global [%0], [%1], 16, %2;\n"
                         :: "r"(dst), "l"(src), "r"(sz));
        }
        asm volatile("cp.async.commit_group;\n");
    };

    stagec(0, 0);
    stagec(1, 1);
    for (int c = 0; c < NC; c++) {
        int st = c & 1;
        if (c + 2 < NC) asm volatile("cp.async.wait_group 1;\n");
        else            asm volatile("cp.async.wait_group 0;\n");
        __syncthreads();

        uint32_t base = sbase + (uint32_t)st * CSTAGE;
        int arow  = wm * 64 + (lane & 15);
        int browp = ((lane >> 4) << 3) + (lane & 7);
        int bchl  = (lane >> 3) & 1;
#pragma unroll
        for (int ks = 0; ks < 4; ks++) {
            // B hi frags (and lo if split)
            uint32_t bh[4][2], bl[4][2];
#pragma unroll
            for (int p = 0; p < 2; p++) {
                int row = wn * 32 + p * 16 + browp;
                int ch  = ks * 2 + bchl;
                uint32_t sw = (uint32_t)((ch ^ (row & 7)) << 4);
                uint32_t t0, t1, t2, t3;
                LDSM_X4(t0, t1, t2, t3, base + 32768u + (uint32_t)row * 128u + sw);
                bh[2*p][0] = t0; bh[2*p][1] = t1; bh[2*p+1][0] = t2; bh[2*p+1][1] = t3;
                if constexpr (BSPLIT) {
                    LDSM_X4(t0, t1, t2, t3, base + 49152u + (uint32_t)row * 128u + sw);
                    bl[2*p][0] = t0; bl[2*p][1] = t1; bl[2*p+1][0] = t2; bl[2*p+1][1] = t3;
                }
            }
            // A hi/lo frags
            uint32_t ah[4][4], al[4][4];
#pragma unroll
            for (int mt = 0; mt < 4; mt++) {
                int row = arow + mt * 16;
                int ch  = ks * 2 + (lane >> 4);
                uint32_t sw = (uint32_t)((ch ^ (row & 7)) << 4);
                LDSM_X4(ah[mt][0], ah[mt][1], ah[mt][2], ah[mt][3],
                        base + (uint32_t)row * 128u + sw);
                LDSM_X4(al[mt][0], al[mt][1], al[mt][2], al[mt][3],
                        base + 16384u + (uint32_t)row * 128u + sw);
            }
#pragma unroll
            for (int mt = 0; mt < 4; mt++)
#pragma unroll
                for (int nt = 0; nt < 4; nt++) {
                    MMA16816(acc[mt][nt], ah[mt], bh[nt]);
                    if constexpr (BSPLIT) MMA16816(acc[mt][nt], ah[mt], bl[nt]);
                    MMA16816(acc[mt][nt], al[mt], bh[nt]);
                    if constexpr (TERMS == 4) MMA16816(acc[mt][nt], al[mt], bl[nt]);
                }
        }
        __syncthreads();
        if (c + 2 < NC) stagec(st, c + 2);
    }

    // --- epilogue: bias + store + per-channel stats ---
    const int gid = lane >> 2, tig = lane & 3;
#pragma unroll
    for (int mt = 0; mt < 4; mt++) {
        int r0 = co0 + wm * 64 + mt * 16 + gid;
        int r1 = r0 + 8;
        float bv0 = bias[r0], bv1 = bias[r1];
        float s0 = 0.0f, q0 = 0.0f, s1 = 0.0f, q1 = 0.0f;
#pragma unroll
        for (int nt = 0; nt < 4; nt++) {
            int l = l0 + wn * 32 + nt * 8 + tig * 2;
            float d0 = acc[mt][nt][0] + bv0, d1 = acc[mt][nt][1] + bv0;
            float d2 = acc[mt][nt][2] + bv1, d3 = acc[mt][nt][3] + bv1;
            *reinterpret_cast<float2*>(&y[((size_t)bb * COUT + r0) * LLEN + l]) = make_float2(d0, d1);
            *reinterpret_cast<float2*>(&y[((size_t)bb * COUT + r1) * LLEN + l]) = make_float2(d2, d3);
            s0 += d0 + d1; q0 = __fmaf_rn(d0, d0, q0); q0 = __fmaf_rn(d1, d1, q0);
            s1 += d2 + d3; q1 = __fmaf_rn(d2, d2, q1); q1 = __fmaf_rn(d3, d3, q1);
        }
#pragma unroll
        for (int off = 1; off < 4; off <<= 1) {
            s0 += __shfl_xor_sync(0xffffffffu, s0, off, 4);
            q0 += __shfl_xor_sync(0xffffffffu, q0, off, 4);
            s1 += __shfl_xor_sync(0xffffffffu, s1, off, 4);
            q1 += __shfl_xor_sync(0xffffffffu, q1, off, 4);
        }
        if (tig == 0) {
            atomicAdd(&stats[2 * r0],     s0);
            atomicAdd(&stats[2 * r0 + 1], q0);
            atomicAdd(&stats[2 * r1],     s1);
            atomicAdd(&stats[2 * r1 + 1], q1);
        }
    }
}

// ---------------- launch ----------------
extern "C" void kernel_launch(void* const* d_in, const int* in_sizes, int n_in,
                              void* d_out, int out_size) {
    const float* x   = (const float*)d_in[0];
    const float* w1  = (const float*)d_in[1];
    const float* b1  = (const float*)d_in[2];
    const float* g1  = (const float*)d_in[3];
    const float* be1 = (const float*)d_in[4];
    const float* w2  = (const float*)d_in[5];
    const float* b2  = (const float*)d_in[6];
    const float* g2  = (const float*)d_in[7];
    const float* be2 = (const float*)d_in[8];
    const float* wd  = (const float*)d_in[9];
    const float* bd  = (const float*)d_in[10];
    const float* gd  = (const float*)d_in[11];
    const float* bed = (const float*)d_in[12];
    float* out = (float*)d_out;
    (void)in_sizes; (void)n_in; (void)out_size;   // T = 8 (hardcoded, shapes fixed)

    float *y1, *y2, *r, *stats;
    __nv_bfloat16 *s1T, *xh, *xl, *A1, *Ad, *A2;
    float2* aff;
    cudaGetSymbolAddress((void**)&y1,  g_y1);
    cudaGetSymbolAddress((void**)&y2,  g_y2);
    cudaGetSymbolAddress((void**)&r,   g_r);
    cudaGetSymbolAddress((void**)&s1T, g_s1T);
    cudaGetSymbolAddress((void**)&xh,  g_xh);
    cudaGetSymbolAddress((void**)&xl,  g_xl);
    cudaGetSymbolAddress((void**)&A1,  g_A1);
    cudaGetSymbolAddress((void**)&Ad,  g_Ad);
    cudaGetSymbolAddress((void**)&A2,  g_A2);
    cudaGetSymbolAddress((void**)&stats, g_stats);
    cudaGetSymbolAddress((void**)&aff, g_aff);

    cudaFuncSetAttribute((const void*)conv_mma_kernel<3, CIN1, 4>,
                         cudaFuncAttributeMaxDynamicSharedMemorySize, 131072);
    cudaFuncSetAttribute((const void*)conv_mma_kernel<1, CIN1, 3>,
                         cudaFuncAttributeMaxDynamicSharedMemorySize, 131072);
    cudaFuncSetAttribute((const void*)conv_mma_kernel<3, COUT, 2>,
                         cudaFuncAttributeMaxDynamicSharedMemorySize, 98304);

    // prep: 98304 + 32768 + 196608 + 1536 = 329216 items
    prep_kernel<<<(329216 + 255)/256, 256>>>(w1, w2, wd, A1, Ad, A2, stats);
    // x -> channel-major hi/lo bf16
    xsplit_kernel<<<dim3(LLEN/64, CIN1/64, BATCH), 256>>>((const float4*)x, xh, xl);

    dim3 cgrid(LLEN/128, COUT/128, BATCH);
    // conv1 (HMMA, 4-term full dbf16 -> fp32-class; feeds LIF1) -> y1 + stats
    conv_mma_kernel<3, CIN1, 4><<<cgrid, 256, 131072>>>(xh, xl, A1, b1, y1, stats);
    // ds conv (HMMA, 3-term; linear path) -> r + stats
    conv_mma_kernel<1, CIN1, 3><<<cgrid, 256, 131072>>>(xh, xl, Ad, bd, r, stats + 1024);
    finalize_bn_kernel<<<1, 256>>>(stats,        g1, be1, aff);                // bn1
    finalize_bn_kernel<<<1, 256>>>(stats + 1024, gd, bed, aff + 512);          // bnd
    // LIF stage 1 -> channel-major bf16 (exact)
    lif_t_kernel<<<dim3(LLEN/64, COUT/64, BATCH), 256>>>((const float4*)y1, aff, s1T);
    // conv2 (HMMA, 2-term, B exact)
    conv_mma_kernel<3, COUT, 2><<<cgrid, 256, 98304>>>(s1T, s1T, A2, b2, y2, stats + 512);
    finalize_bn_kernel<<<1, 256>>>(stats + 512, g2, be2, aff + 256);           // bn2
    final_kernel<<<NELEM/1024, 256>>>((const float4*)y2, (const float4*)r,
                                      aff + 256, aff + 512, (float4*)out);
}